// round 1
// baseline (speedup 1.0000x reference)
#include <cuda_runtime.h>
#include <math.h>

// ---------------- scratch (device globals: allocation-free) ----------------
__device__ float g_K1[32 * 25];               // conv1 dense kernel (oc,5,5)
__device__ float g_K2T[800 * 64];             // conv2 kernel transposed: [(ic*25+ky*5+kx)][oc]
__device__ float g_h1[4096 * 32 * 14 * 14];   // pooled conv1 output
__device__ float g_h2[4096 * 64 * 7 * 7];     // pooled conv2 output
__device__ float g_f1[4096 * 128];            // fc1 output

// ---------------- DCLS dense-kernel builders (deterministic, no atomics) ----
__global__ void build_k1_dense(const float* __restrict__ w1, const float* __restrict__ p1) {
    int t = blockIdx.x * 256 + threadIdx.x;
    if (t >= 32 * 25) return;
    int co = t / 25; int cell = t - co * 25;
    int ii = cell / 5, jj = cell - ii * 5;
    float s = 0.f;
    #pragma unroll 4
    for (int kc = 0; kc < 16; kc++) {
        int e = co * 16 + kc;
        float w  = w1[e];
        float pa = fminf(fmaxf(p1[e],       -2.f), 2.f) + 2.f;
        float pb = fminf(fmaxf(p1[512 + e], -2.f), 2.f) + 2.f;
        int i1 = (int)floorf(pa), i2 = (int)floorf(pb);
        float r1 = pa - (float)i1, r2 = pb - (float)i2;
        if (i1     == ii && i2     == jj) s += w * (1.f - r1) * (1.f - r2);
        if (i1 + 1 == ii && i2     == jj) s += w * r1 * (1.f - r2);
        if (i1     == ii && i2 + 1 == jj) s += w * (1.f - r1) * r2;
        if (i1 + 1 == ii && i2 + 1 == jj) s += w * r1 * r2;
    }
    g_K1[t] = s;
}

__global__ void build_k2_dense(const float* __restrict__ w2, const float* __restrict__ p2) {
    int t = blockIdx.x * 256 + threadIdx.x;   // t indexes g_K2T directly
    if (t >= 800 * 64) return;
    int co = t & 63;
    int q  = t >> 6;          // ic*25 + cell
    int ci = q / 25; int cell = q - ci * 25;
    int ii = cell / 5, jj = cell - ii * 5;
    float s = 0.f;
    #pragma unroll 4
    for (int kc = 0; kc < 32; kc++) {
        int e = co * 1024 + ci * 32 + kc;
        float w  = w2[e];
        float pa = fminf(fmaxf(p2[e],         -2.f), 2.f) + 2.f;
        float pb = fminf(fmaxf(p2[65536 + e], -2.f), 2.f) + 2.f;
        int i1 = (int)floorf(pa), i2 = (int)floorf(pb);
        float r1 = pa - (float)i1, r2 = pb - (float)i2;
        if (i1     == ii && i2     == jj) s += w * (1.f - r1) * (1.f - r2);
        if (i1 + 1 == ii && i2     == jj) s += w * r1 * (1.f - r2);
        if (i1     == ii && i2 + 1 == jj) s += w * (1.f - r1) * r2;
        if (i1 + 1 == ii && i2 + 1 == jj) s += w * r1 * r2;
    }
    g_K2T[t] = s;
}

// ---------------- conv1 (1->32, 5x5, pad2) + relu + maxpool2 ----------------
// one block per image; 256 threads
__global__ __launch_bounds__(256) void conv1_kernel(const float* __restrict__ x,
                                                    const float* __restrict__ b1) {
    __shared__ float sImg[32][32];    // 28x28 with halo 2 (pad)
    __shared__ float sK[800];
    __shared__ float sB[32];
    int b = blockIdx.x;
    int tid = threadIdx.x;

    for (int i = tid; i < 1024; i += 256) ((float*)sImg)[i] = 0.f;
    for (int i = tid; i < 800;  i += 256) sK[i] = g_K1[i];
    if (tid < 32) sB[tid] = b1[tid];
    __syncthreads();
    const float* xb = x + (long)b * 784;
    for (int i = tid; i < 784; i += 256) {
        int r = i / 28, c = i - r * 28;
        sImg[r + 2][c + 2] = xb[i];
    }
    __syncthreads();

    float* out = g_h1 + (long)b * 6272;
    for (int o = tid; o < 6272; o += 256) {
        int oc = o / 196; int p = o - oc * 196;
        int pi = p / 14, pj = p - pi * 14;
        int r0 = 2 * pi, c0 = 2 * pj;
        const float* kp = &sK[oc * 25];
        float a00 = 0.f, a01 = 0.f, a10 = 0.f, a11 = 0.f;
        #pragma unroll
        for (int ky = 0; ky < 5; ky++) {
            #pragma unroll
            for (int kx = 0; kx < 5; kx++) {
                float kw = kp[ky * 5 + kx];
                a00 += kw * sImg[r0 + ky][c0 + kx];
                a01 += kw * sImg[r0 + ky][c0 + kx + 1];
                a10 += kw * sImg[r0 + 1 + ky][c0 + kx];
                a11 += kw * sImg[r0 + 1 + ky][c0 + kx + 1];
            }
        }
        float m = fmaxf(fmaxf(a00, a01), fmaxf(a10, a11)) + sB[oc];
        out[o] = fmaxf(m, 0.f);
    }
}

// ---------------- conv2 (32->64, 5x5, pad2) + relu + maxpool2 ----------------
// grid (4096, 2): block = (image, 32-oc half). 256 threads = 64 pos-slots x 4 oc-groups(8 oc each).
// dynamic smem: sIn[32][18][18] (haloed input) + sKT[800][32] + sB[32] = 144128 B
__global__ __launch_bounds__(256) void conv2_kernel(const float* __restrict__ b2) {
    extern __shared__ float sm[];
    float* sIn = sm;                    // 32*18*18 = 10368
    float* sKT = sm + 10368;            // 800*32  = 25600
    float* sB  = sKT + 25600;           // 32
    int b = blockIdx.x;
    int ocBase = blockIdx.y * 32;
    int tid = threadIdx.x;

    for (int i = tid; i < 10368; i += 256) sIn[i] = 0.f;
    for (int i = tid; i < 25600; i += 256) {
        int kk = i >> 5; int oc = i & 31;
        sKT[i] = g_K2T[kk * 64 + ocBase + oc];   // coalesced 32-float rows
    }
    if (tid < 32) sB[tid] = b2[ocBase + tid];
    __syncthreads();
    const float* hb = g_h1 + (long)b * 6272;
    for (int i = tid; i < 6272; i += 256) {
        int ic = i / 196; int p = i - ic * 196;
        int r = p / 14, c = p - r * 14;
        sIn[ic * 324 + (r + 2) * 18 + (c + 2)] = hb[i];
    }
    __syncthreads();

    int pos = tid & 63;
    int ocg = tid >> 6;              // 0..3 -> oc ocBase+ocg*8 .. +7
    if (pos >= 49) return;
    int pi = pos / 7, pj = pos - pi * 7;
    int r0 = 2 * pi, c0 = 2 * pj;

    float acc[4][8];
    #pragma unroll
    for (int q = 0; q < 4; q++)
        #pragma unroll
        for (int o = 0; o < 8; o++) acc[q][o] = 0.f;

    for (int ic = 0; ic < 32; ic++) {
        const float* row = sIn + ic * 324;
        #pragma unroll
        for (int ky = 0; ky < 5; ky++) {
            const float* rA = row + (r0 + ky) * 18 + c0;
            const float* rB = rA + 18;
            #pragma unroll
            for (int kx = 0; kx < 5; kx++) {
                int kk = ic * 25 + ky * 5 + kx;
                const float* kp = &sKT[kk * 32 + ocg * 8];
                float kv[8];
                *(float4*)&kv[0] = *(const float4*)&kp[0];
                *(float4*)&kv[4] = *(const float4*)&kp[4];
                float xv[4];
                xv[0] = rA[kx]; xv[1] = rA[kx + 1];
                xv[2] = rB[kx]; xv[3] = rB[kx + 1];
                #pragma unroll
                for (int q = 0; q < 4; q++)
                    #pragma unroll
                    for (int o = 0; o < 8; o++)
                        acc[q][o] += xv[q] * kv[o];
            }
        }
    }

    float* out = g_h2 + (long)b * 3136;
    #pragma unroll
    for (int o = 0; o < 8; o++) {
        float m = fmaxf(fmaxf(acc[0][o], acc[1][o]), fmaxf(acc[2][o], acc[3][o]))
                  + sB[ocg * 8 + o];
        out[(ocBase + ocg * 8 + o) * 49 + pi * 7 + pj] = fmaxf(m, 0.f);
    }
}

// ---------------- FC1: (4096,3136) @ (128,3136)^T + bias, relu ----------------
// BM=64, BN=64, BK=16, 256 threads, 4x4 per thread. grid (64, 2).
__global__ __launch_bounds__(256) void fc1_kernel(const float* __restrict__ w,
                                                  const float* __restrict__ bias) {
    __shared__ float sA[16][68];   // [k][m], pad 68 (272B, 16B-aligned rows)
    __shared__ float sW[16][68];   // [k][n]
    int tid = threadIdx.x;
    int tx = tid & 15;            // n group
    int ty = tid >> 4;            // m group
    int mBase = blockIdx.x * 64;
    int nBase = blockIdx.y * 64;

    int lrow = tid >> 2;          // 0..63
    int lk   = (tid & 3) * 4;     // 0,4,8,12

    const float* A = g_h2;
    float acc[4][4];
    #pragma unroll
    for (int i = 0; i < 4; i++)
        #pragma unroll
        for (int j = 0; j < 4; j++) acc[i][j] = 0.f;

    for (int kt = 0; kt < 3136; kt += 16) {
        float4 a4 = *(const float4*)&A[(long)(mBase + lrow) * 3136 + kt + lk];
        float4 w4 = *(const float4*)&w[(long)(nBase + lrow) * 3136 + kt + lk];
        float av[4] = {a4.x, a4.y, a4.z, a4.w};
        float wv[4] = {w4.x, w4.y, w4.z, w4.w};
        #pragma unroll
        for (int q = 0; q < 4; q++) {
            sA[lk + q][lrow] = av[q];
            sW[lk + q][lrow] = wv[q];
        }
        __syncthreads();
        #pragma unroll
        for (int kk = 0; kk < 16; kk++) {
            float4 a = *(const float4*)&sA[kk][ty * 4];
            float4 bb = *(const float4*)&sW[kk][tx * 4];
            float ar[4] = {a.x, a.y, a.z, a.w};
            float br[4] = {bb.x, bb.y, bb.z, bb.w};
            #pragma unroll
            for (int i = 0; i < 4; i++)
                #pragma unroll
                for (int j = 0; j < 4; j++)
                    acc[i][j] += ar[i] * br[j];
        }
        __syncthreads();
    }

    #pragma unroll
    for (int i = 0; i < 4; i++) {
        int m = mBase + ty * 4 + i;
        #pragma unroll
        for (int j = 0; j < 4; j++) {
            int n = nBase + tx * 4 + j;
            float v = acc[i][j] + bias[n];
            g_f1[(long)m * 128 + n] = fmaxf(v, 0.f);
        }
    }
}

// ---------------- FC2: (4096,128) @ (10,128)^T + bias ----------------
__global__ __launch_bounds__(256) void fc2_kernel(const float* __restrict__ w,
                                                  const float* __restrict__ bias,
                                                  float* __restrict__ out) {
    int idx = blockIdx.x * 256 + threadIdx.x;
    if (idx >= 4096 * 10) return;
    int b = idx / 10, n = idx - b * 10;
    const float* h  = g_f1 + (long)b * 128;
    const float* wr = w + n * 128;
    float s = bias[n];
    #pragma unroll 8
    for (int k = 0; k < 128; k++) s += h[k] * wr[k];
    out[idx] = s;
}

// ---------------- launcher ----------------
extern "C" void kernel_launch(void* const* d_in, const int* in_sizes, int n_in,
                              void* d_out, int out_size) {
    const float* x     = (const float*)d_in[0];
    const float* w1    = (const float*)d_in[1];
    const float* p1    = (const float*)d_in[2];
    const float* b1    = (const float*)d_in[3];
    const float* w2    = (const float*)d_in[4];
    const float* p2    = (const float*)d_in[5];
    const float* b2    = (const float*)d_in[6];
    const float* fc1w  = (const float*)d_in[7];
    const float* fc1b  = (const float*)d_in[8];
    const float* fc2w  = (const float*)d_in[9];
    const float* fc2b  = (const float*)d_in[10];
    float* out = (float*)d_out;

    build_k1_dense<<<4, 256>>>(w1, p1);
    build_k2_dense<<<200, 256>>>(w2, p2);
    conv1_kernel<<<4096, 256>>>(x, b1);

    static const int conv2_smem = (10368 + 25600 + 32) * 4;   // 144128 B
    cudaFuncSetAttribute(conv2_kernel, cudaFuncAttributeMaxDynamicSharedMemorySize, conv2_smem);
    conv2_kernel<<<dim3(4096, 2), 256, conv2_smem>>>(b2);

    fc1_kernel<<<dim3(64, 2), 256>>>(fc1w, fc1b);
    fc2_kernel<<<160, 256>>>(fc2w, fc2b, out);
}

// round 2
// speedup vs baseline: 1.1122x; 1.1122x over previous
#include <cuda_runtime.h>
#include <math.h>

// ---------------- scratch (device globals: allocation-free) ----------------
__device__ float g_K1[32 * 25];               // conv1 dense kernel (oc,5,5)
__device__ float g_K2T[800 * 64];             // conv2 kernel transposed: [(ic*25+ky*5+kx)][oc]
__device__ float g_h1[4096 * 32 * 14 * 14];   // pooled conv1 output [b][ic][14][14]
__device__ float g_h2[4096 * 64 * 7 * 7];     // pooled conv2 output, PERMUTED: [b][pos(49)][oc(64)]
__device__ float g_f1[4096 * 128];            // fc1 output
__device__ float g_fc1wP[128 * 3136];         // fc1 weight permuted to [n][pos*64+oc]

// ---------------- DCLS dense-kernel builders (deterministic, no atomics) ----
__global__ void build_k1_dense(const float* __restrict__ w1, const float* __restrict__ p1) {
    int t = blockIdx.x * 256 + threadIdx.x;
    if (t >= 32 * 25) return;
    int co = t / 25; int cell = t - co * 25;
    int ii = cell / 5, jj = cell - ii * 5;
    float s = 0.f;
    #pragma unroll 4
    for (int kc = 0; kc < 16; kc++) {
        int e = co * 16 + kc;
        float w  = w1[e];
        float pa = fminf(fmaxf(p1[e],       -2.f), 2.f) + 2.f;
        float pb = fminf(fmaxf(p1[512 + e], -2.f), 2.f) + 2.f;
        int i1 = (int)floorf(pa), i2 = (int)floorf(pb);
        float r1 = pa - (float)i1, r2 = pb - (float)i2;
        if (i1     == ii && i2     == jj) s += w * (1.f - r1) * (1.f - r2);
        if (i1 + 1 == ii && i2     == jj) s += w * r1 * (1.f - r2);
        if (i1     == ii && i2 + 1 == jj) s += w * (1.f - r1) * r2;
        if (i1 + 1 == ii && i2 + 1 == jj) s += w * r1 * r2;
    }
    g_K1[t] = s;
}

__global__ void build_k2_dense(const float* __restrict__ w2, const float* __restrict__ p2) {
    int t = blockIdx.x * 256 + threadIdx.x;   // t indexes g_K2T directly
    if (t >= 800 * 64) return;
    int co = t & 63;
    int q  = t >> 6;          // ic*25 + cell
    int ci = q / 25; int cell = q - ci * 25;
    int ii = cell / 5, jj = cell - ii * 5;
    float s = 0.f;
    #pragma unroll 4
    for (int kc = 0; kc < 32; kc++) {
        int e = co * 1024 + ci * 32 + kc;
        float w  = w2[e];
        float pa = fminf(fmaxf(p2[e],         -2.f), 2.f) + 2.f;
        float pb = fminf(fmaxf(p2[65536 + e], -2.f), 2.f) + 2.f;
        int i1 = (int)floorf(pa), i2 = (int)floorf(pb);
        float r1 = pa - (float)i1, r2 = pb - (float)i2;
        if (i1     == ii && i2     == jj) s += w * (1.f - r1) * (1.f - r2);
        if (i1 + 1 == ii && i2     == jj) s += w * r1 * (1.f - r2);
        if (i1     == ii && i2 + 1 == jj) s += w * (1.f - r1) * r2;
        if (i1 + 1 == ii && i2 + 1 == jj) s += w * r1 * r2;
    }
    g_K2T[t] = s;
}

// ---------------- fc1 weight permute: [n][oc*49+p] -> [n][p*64+oc] ----------
__global__ void permute_fc1w(const float* __restrict__ w) {
    int idx = blockIdx.x * 256 + threadIdx.x;
    if (idx >= 128 * 3136) return;
    int n = idx / 3136; int j = idx - n * 3136;
    int p = j >> 6, oc = j & 63;
    g_fc1wP[idx] = w[n * 3136 + oc * 49 + p];
}

// ---------------- conv1 (1->32, 5x5, pad2) + relu + maxpool2 ----------------
__global__ __launch_bounds__(256) void conv1_kernel(const float* __restrict__ x,
                                                    const float* __restrict__ b1) {
    __shared__ float sImg[32][32];    // 28x28 with halo 2 (pad)
    __shared__ float sK[800];
    __shared__ float sB[32];
    int b = blockIdx.x;
    int tid = threadIdx.x;

    for (int i = tid; i < 1024; i += 256) ((float*)sImg)[i] = 0.f;
    for (int i = tid; i < 800;  i += 256) sK[i] = g_K1[i];
    if (tid < 32) sB[tid] = b1[tid];
    __syncthreads();
    const float* xb = x + (long)b * 784;
    for (int i = tid; i < 784; i += 256) {
        int r = i / 28, c = i - r * 28;
        sImg[r + 2][c + 2] = xb[i];
    }
    __syncthreads();

    float* out = g_h1 + (long)b * 6272;
    for (int o = tid; o < 6272; o += 256) {
        int oc = o / 196; int p = o - oc * 196;
        int pi = p / 14, pj = p - pi * 14;
        int r0 = 2 * pi, c0 = 2 * pj;
        const float* kp = &sK[oc * 25];
        float a00 = 0.f, a01 = 0.f, a10 = 0.f, a11 = 0.f;
        #pragma unroll
        for (int ky = 0; ky < 5; ky++) {
            #pragma unroll
            for (int kx = 0; kx < 5; kx++) {
                float kw = kp[ky * 5 + kx];
                a00 += kw * sImg[r0 + ky][c0 + kx];
                a01 += kw * sImg[r0 + ky][c0 + kx + 1];
                a10 += kw * sImg[r0 + 1 + ky][c0 + kx];
                a11 += kw * sImg[r0 + 1 + ky][c0 + kx + 1];
            }
        }
        float m = fmaxf(fmaxf(a00, a01), fmaxf(a10, a11)) + sB[oc];
        out[o] = fmaxf(m, 0.f);
    }
}

// ---------------- conv2 (32->64, 5x5, pad2) + relu + maxpool2 ----------------
// grid (4096, 2): (image, 32-oc half). 448 threads = 14 warps.
// warp = pre-pool output row r (0..13); lane = oc (0..31).
// Each thread computes a full 14-wide pre-pool row in registers.
// smem: sIn[32][18][20] (haloed, stride-padded) = 11520 floats,
//       sK chunk [8*25][32] = 6400 floats. Total 17920 floats = 71680 B -> 2 CTA/SM.
__global__ __launch_bounds__(448, 2) void conv2_kernel(const float* __restrict__ b2) {
    extern __shared__ float sm[];
    float* sIn = sm;            // 11520
    float* sK  = sm + 11520;    // 6400
    int b = blockIdx.x;
    int ocBase = blockIdx.y * 32;
    int tid = threadIdx.x;
    int lane = tid & 31;        // oc within half
    int r    = tid >> 5;        // 0..13 pre-pool row

    // zero halo + fill interior
    for (int i = tid; i < 11520; i += 448) sIn[i] = 0.f;
    __syncthreads();
    const float* hb = g_h1 + (long)b * 6272;
    for (int i = tid; i < 6272; i += 448) {
        int ic = i / 196; int p = i - ic * 196;
        int rr = p / 14, cc = p - rr * 14;
        sIn[ic * 360 + (rr + 2) * 20 + cc + 2] = hb[i];
    }

    float acc[14];
    #pragma unroll
    for (int c = 0; c < 14; c++) acc[c] = 0.f;

    for (int chunk = 0; chunk < 4; chunk++) {
        __syncthreads();   // sIn ready (first iter) / previous chunk compute done
        for (int i = tid; i < 6400; i += 448) {
            int kkl = i >> 5; int oc = i & 31;
            sK[i] = g_K2T[(chunk * 200 + kkl) * 64 + ocBase + oc];
        }
        __syncthreads();

        for (int icl = 0; icl < 8; icl++) {
            const float* base = sIn + (chunk * 8 + icl) * 360;
            #pragma unroll
            for (int ky = 0; ky < 5; ky++) {
                const float* row = base + (r + ky) * 20;
                float x[20];
                #pragma unroll
                for (int q = 0; q < 5; q++)
                    *(float4*)&x[q * 4] = *(const float4*)&row[q * 4];
                const float* kp = sK + (icl * 25 + ky * 5) * 32 + lane;
                float k0 = kp[0], k1 = kp[32], k2 = kp[64], k3 = kp[96], k4 = kp[128];
                #pragma unroll
                for (int c = 0; c < 14; c++)
                    acc[c] += k0 * x[c] + k1 * x[c + 1] + k2 * x[c + 2]
                            + k3 * x[c + 3] + k4 * x[c + 4];
            }
        }
    }

    // epilogue: transpose rows into smem, pool 2x2, relu, store permuted [p][oc]
    __syncthreads();
    float* sP = sIn;   // reuse: [14][14][32] = 6272 floats
    #pragma unroll
    for (int c = 0; c < 14; c++)
        sP[(r * 14 + c) * 32 + lane] = acc[c];
    __syncthreads();

    float* out = g_h2 + (long)b * 3136;
    for (int i = tid; i < 1568; i += 448) {
        int oc = i & 31; int p = i >> 5;   // p in 0..48
        int pi = p / 7, pj = p - pi * 7;
        int r0 = 2 * pi, c0 = 2 * pj;
        float m = fmaxf(fmaxf(sP[(r0 * 14 + c0) * 32 + oc],
                              sP[(r0 * 14 + c0 + 1) * 32 + oc]),
                        fmaxf(sP[((r0 + 1) * 14 + c0) * 32 + oc],
                              sP[((r0 + 1) * 14 + c0 + 1) * 32 + oc]));
        m += b2[ocBase + oc];
        out[p * 64 + ocBase + oc] = fmaxf(m, 0.f);
    }
}

// ---------------- FC1: (4096,3136) @ (128,3136)^T + bias, relu ----------------
// BM=64, BN=64, BK=16, 256 threads, 4x4 per thread. grid (64, 2). Uses permuted W.
__global__ __launch_bounds__(256) void fc1_kernel(const float* __restrict__ bias) {
    __shared__ float sA[16][68];
    __shared__ float sW[16][68];
    int tid = threadIdx.x;
    int tx = tid & 15;
    int ty = tid >> 4;
    int mBase = blockIdx.x * 64;
    int nBase = blockIdx.y * 64;

    int lrow = tid >> 2;
    int lk   = (tid & 3) * 4;

    const float* A = g_h2;
    const float* w = g_fc1wP;
    float acc[4][4];
    #pragma unroll
    for (int i = 0; i < 4; i++)
        #pragma unroll
        for (int j = 0; j < 4; j++) acc[i][j] = 0.f;

    for (int kt = 0; kt < 3136; kt += 16) {
        float4 a4 = *(const float4*)&A[(long)(mBase + lrow) * 3136 + kt + lk];
        float4 w4 = *(const float4*)&w[(long)(nBase + lrow) * 3136 + kt + lk];
        float av[4] = {a4.x, a4.y, a4.z, a4.w};
        float wv[4] = {w4.x, w4.y, w4.z, w4.w};
        #pragma unroll
        for (int q = 0; q < 4; q++) {
            sA[lk + q][lrow] = av[q];
            sW[lk + q][lrow] = wv[q];
        }
        __syncthreads();
        #pragma unroll
        for (int kk = 0; kk < 16; kk++) {
            float4 a = *(const float4*)&sA[kk][ty * 4];
            float4 bb = *(const float4*)&sW[kk][tx * 4];
            float ar[4] = {a.x, a.y, a.z, a.w};
            float br[4] = {bb.x, bb.y, bb.z, bb.w};
            #pragma unroll
            for (int i = 0; i < 4; i++)
                #pragma unroll
                for (int j = 0; j < 4; j++)
                    acc[i][j] += ar[i] * br[j];
        }
        __syncthreads();
    }

    #pragma unroll
    for (int i = 0; i < 4; i++) {
        int m = mBase + ty * 4 + i;
        #pragma unroll
        for (int j = 0; j < 4; j++) {
            int n = nBase + tx * 4 + j;
            float v = acc[i][j] + bias[n];
            g_f1[(long)m * 128 + n] = fmaxf(v, 0.f);
        }
    }
}

// ---------------- FC2: (4096,128) @ (10,128)^T + bias ----------------
__global__ __launch_bounds__(256) void fc2_kernel(const float* __restrict__ w,
                                                  const float* __restrict__ bias,
                                                  float* __restrict__ out) {
    int idx = blockIdx.x * 256 + threadIdx.x;
    if (idx >= 4096 * 10) return;
    int b = idx / 10, n = idx - b * 10;
    const float* h  = g_f1 + (long)b * 128;
    const float* wr = w + n * 128;
    float s = bias[n];
    #pragma unroll 8
    for (int k = 0; k < 128; k++) s += h[k] * wr[k];
    out[idx] = s;
}

// ---------------- launcher ----------------
extern "C" void kernel_launch(void* const* d_in, const int* in_sizes, int n_in,
                              void* d_out, int out_size) {
    const float* x     = (const float*)d_in[0];
    const float* w1    = (const float*)d_in[1];
    const float* p1    = (const float*)d_in[2];
    const float* b1    = (const float*)d_in[3];
    const float* w2    = (const float*)d_in[4];
    const float* p2    = (const float*)d_in[5];
    const float* b2    = (const float*)d_in[6];
    const float* fc1w  = (const float*)d_in[7];
    const float* fc1b  = (const float*)d_in[8];
    const float* fc2w  = (const float*)d_in[9];
    const float* fc2b  = (const float*)d_in[10];
    float* out = (float*)d_out;

    build_k1_dense<<<4, 256>>>(w1, p1);
    build_k2_dense<<<200, 256>>>(w2, p2);
    permute_fc1w<<<(128 * 3136 + 255) / 256, 256>>>(fc1w);
    conv1_kernel<<<4096, 256>>>(x, b1);

    static const int conv2_smem = (11520 + 6400) * 4;   // 71680 B
    cudaFuncSetAttribute(conv2_kernel, cudaFuncAttributeMaxDynamicSharedMemorySize, conv2_smem);
    conv2_kernel<<<dim3(4096, 2), 448, conv2_smem>>>(b2);

    fc1_kernel<<<dim3(64, 2), 256>>>(fc1b);
    fc2_kernel<<<160, 256>>>(fc2w, fc2b, out);
}

// round 3
// speedup vs baseline: 1.1687x; 1.0508x over previous
#include <cuda_runtime.h>
#include <math.h>

// ---------------- scratch (device globals: allocation-free) ----------------
__device__ float g_K1T[25 * 32];              // conv1 dense kernel TRANSPOSED [tap][oc]
__device__ float g_K2T[800 * 64];             // conv2 kernel transposed: [(ic*25+ky*5+kx)][oc]
__device__ float g_h1[4096 * 196 * 32];       // pooled conv1 output, pos-major: [b][pos(196)][ic(32)]
__device__ float g_h2[4096 * 64 * 7 * 7];     // pooled conv2 output, pos-major: [b][pos(49)][oc(64)]
__device__ float g_f1[4096 * 128];            // fc1 output
__device__ float g_fc1wP[128 * 3136];         // fc1 weight permuted to [n][pos*64+oc]

// ---------------- cp.async helpers ----------------
__device__ __forceinline__ unsigned smem_u32(const void* p) {
    return (unsigned)__cvta_generic_to_shared(p);
}
#define CP_ASYNC16(dst_u32, src_ptr) \
    asm volatile("cp.async.cg.shared.global [%0], [%1], 16;" :: "r"(dst_u32), "l"(src_ptr))
#define CP_COMMIT() asm volatile("cp.async.commit_group;")
#define CP_WAIT_ALL() asm volatile("cp.async.wait_group 0;" ::: "memory")

// ---------------- DCLS dense-kernel builders (deterministic, no atomics) ----
__global__ void build_k1_dense(const float* __restrict__ w1, const float* __restrict__ p1) {
    int t = blockIdx.x * 256 + threadIdx.x;
    if (t >= 32 * 25) return;
    int co = t / 25; int cell = t - co * 25;
    int ii = cell / 5, jj = cell - ii * 5;
    float s = 0.f;
    #pragma unroll 4
    for (int kc = 0; kc < 16; kc++) {
        int e = co * 16 + kc;
        float w  = w1[e];
        float pa = fminf(fmaxf(p1[e],       -2.f), 2.f) + 2.f;
        float pb = fminf(fmaxf(p1[512 + e], -2.f), 2.f) + 2.f;
        int i1 = (int)floorf(pa), i2 = (int)floorf(pb);
        float r1 = pa - (float)i1, r2 = pb - (float)i2;
        if (i1     == ii && i2     == jj) s += w * (1.f - r1) * (1.f - r2);
        if (i1 + 1 == ii && i2     == jj) s += w * r1 * (1.f - r2);
        if (i1     == ii && i2 + 1 == jj) s += w * (1.f - r1) * r2;
        if (i1 + 1 == ii && i2 + 1 == jj) s += w * r1 * r2;
    }
    g_K1T[cell * 32 + co] = s;
}

__global__ void build_k2_dense(const float* __restrict__ w2, const float* __restrict__ p2) {
    int t = blockIdx.x * 256 + threadIdx.x;   // t indexes g_K2T directly
    if (t >= 800 * 64) return;
    int co = t & 63;
    int q  = t >> 6;          // ic*25 + cell
    int ci = q / 25; int cell = q - ci * 25;
    int ii = cell / 5, jj = cell - ii * 5;
    float s = 0.f;
    #pragma unroll 4
    for (int kc = 0; kc < 32; kc++) {
        int e = co * 1024 + ci * 32 + kc;
        float w  = w2[e];
        float pa = fminf(fmaxf(p2[e],         -2.f), 2.f) + 2.f;
        float pb = fminf(fmaxf(p2[65536 + e], -2.f), 2.f) + 2.f;
        int i1 = (int)floorf(pa), i2 = (int)floorf(pb);
        float r1 = pa - (float)i1, r2 = pb - (float)i2;
        if (i1     == ii && i2     == jj) s += w * (1.f - r1) * (1.f - r2);
        if (i1 + 1 == ii && i2     == jj) s += w * r1 * (1.f - r2);
        if (i1     == ii && i2 + 1 == jj) s += w * (1.f - r1) * r2;
        if (i1 + 1 == ii && i2 + 1 == jj) s += w * r1 * r2;
    }
    g_K2T[t] = s;
}

// ---------------- fc1 weight permute: [n][oc*49+p] -> [n][p*64+oc] ----------
__global__ void permute_fc1w(const float* __restrict__ w) {
    int idx = blockIdx.x * 256 + threadIdx.x;
    if (idx >= 128 * 3136) return;
    int n = idx / 3136; int j = idx - n * 3136;
    int p = j >> 6, oc = j & 63;
    g_fc1wP[idx] = w[n * 3136 + oc * 49 + p];
}

// ---------------- conv1 (1->32, 5x5, pad2) + relu + maxpool2 ----------------
// block = 1 image, 448 threads = 14 warps. warp t = pooled row; lane = oc.
// Register sliding window: each thread computes conv rows 2t and 2t+1 (28 wide),
// pools in registers, stores pos-major [p][oc] coalesced.
__global__ __launch_bounds__(448, 2) void conv1_kernel(const float* __restrict__ x,
                                                       const float* __restrict__ b1) {
    __shared__ float sImg[32][32];    // 28x28 with halo 2 (zero pad)
    __shared__ float sK[800];         // [tap(25)][oc(32)]
    int b = blockIdx.x;
    int tid = threadIdx.x;
    int lane = tid & 31;
    int t = tid >> 5;                 // pooled row 0..13

    for (int i = tid; i < 1024; i += 448) ((float*)sImg)[i] = 0.f;
    for (int i = tid; i < 800;  i += 448) sK[i] = g_K1T[i];
    __syncthreads();
    const float* xb = x + (long)b * 784;
    for (int i = tid; i < 784; i += 448) {
        int r = i / 28, c = i - r * 28;
        sImg[r + 2][c + 2] = xb[i];
    }
    __syncthreads();

    float pr[14];
    #pragma unroll
    for (int rowSel = 0; rowSel < 2; rowSel++) {
        int r = 2 * t + rowSel;       // conv output row 0..27
        float acc[28];
        #pragma unroll
        for (int c = 0; c < 28; c++) acc[c] = 0.f;
        #pragma unroll
        for (int ky = 0; ky < 5; ky++) {
            const float* xr = &sImg[r + ky][0];
            float xv[32];
            #pragma unroll
            for (int q = 0; q < 8; q++)
                *(float4*)&xv[q * 4] = *(const float4*)&xr[q * 4];
            const float* kp = &sK[(ky * 5) * 32 + lane];
            float k0 = kp[0], k1 = kp[32], k2 = kp[64], k3 = kp[96], k4 = kp[128];
            #pragma unroll
            for (int c = 0; c < 28; c++)
                acc[c] += k0 * xv[c] + k1 * xv[c + 1] + k2 * xv[c + 2]
                        + k3 * xv[c + 3] + k4 * xv[c + 4];
        }
        #pragma unroll
        for (int j = 0; j < 14; j++) {
            float m = fmaxf(acc[2 * j], acc[2 * j + 1]);
            pr[j] = rowSel ? fmaxf(pr[j], m) : m;
        }
    }

    float bias = b1[lane];
    float* out = g_h1 + (long)b * 6272;
    #pragma unroll
    for (int j = 0; j < 14; j++)
        out[(t * 14 + j) * 32 + lane] = fmaxf(pr[j] + bias, 0.f);
}

// ---------------- conv2 (32->64, 5x5, pad2) + relu + maxpool2 ----------------
// grid (4096, 2): (image, 32-oc half). 448 threads = 14 warps.
// warp = pre-pool row; lane = oc. Register sliding window, 14-wide row per thread.
// sK double-buffered via cp.async (4 chunks of 8 ic), overlapped with compute.
// smem: sIn[32][18][20] = 11520 + 2 x sK[200][32] = 12800 -> 24320 floats = 97280 B (2 CTA/SM)
__global__ __launch_bounds__(448, 2) void conv2_kernel(const float* __restrict__ b2) {
    extern __shared__ float sm[];
    float* sIn = sm;                 // 11520
    float* sKb[2] = { sm + 11520, sm + 11520 + 6400 };
    int b = blockIdx.x;
    int ocBase = blockIdx.y * 32;
    int tid = threadIdx.x;
    int lane = tid & 31;
    int r    = tid >> 5;             // 0..13 pre-pool row

    // prefetch sK chunk 0
    {
        unsigned dst = smem_u32(sKb[0]);
        for (int i = tid; i < 1600; i += 448) {
            int kkl = i >> 3, ocq = i & 7;
            const float* src = g_K2T + ((0 * 200 + kkl) * 64 + ocBase + ocq * 4);
            CP_ASYNC16(dst + (unsigned)((kkl * 32 + ocq * 4) * 4), src);
        }
        CP_COMMIT();
    }

    // fill sIn (zero halo + interior) — g_h1 is pos-major [p][ic]
    for (int i = tid; i < 11520; i += 448) sIn[i] = 0.f;
    __syncthreads();
    const float* hb = g_h1 + (long)b * 6272;
    for (int i = tid; i < 6272; i += 448) {
        int ic = i & 31; int p = i >> 5;
        int rr = p / 14, cc = p - rr * 14;
        sIn[ic * 360 + (rr + 2) * 20 + cc + 2] = hb[i];
    }

    float acc[14];
    #pragma unroll
    for (int c = 0; c < 14; c++) acc[c] = 0.f;

    for (int chunk = 0; chunk < 4; chunk++) {
        CP_WAIT_ALL();
        __syncthreads();   // sK[chunk&1] visible; sIn ready (iter 0); prev compute done
        if (chunk < 3) {
            unsigned dst = smem_u32(sKb[(chunk + 1) & 1]);
            for (int i = tid; i < 1600; i += 448) {
                int kkl = i >> 3, ocq = i & 7;
                const float* src = g_K2T + (((chunk + 1) * 200 + kkl) * 64 + ocBase + ocq * 4);
                CP_ASYNC16(dst + (unsigned)((kkl * 32 + ocq * 4) * 4), src);
            }
            CP_COMMIT();
        }
        const float* sK = sKb[chunk & 1];

        for (int icl = 0; icl < 8; icl++) {
            const float* base = sIn + (chunk * 8 + icl) * 360;
            #pragma unroll
            for (int ky = 0; ky < 5; ky++) {
                const float* row = base + (r + ky) * 20;
                float xv[20];
                #pragma unroll
                for (int q = 0; q < 5; q++)
                    *(float4*)&xv[q * 4] = *(const float4*)&row[q * 4];
                const float* kp = sK + (icl * 25 + ky * 5) * 32 + lane;
                float k0 = kp[0], k1 = kp[32], k2 = kp[64], k3 = kp[96], k4 = kp[128];
                #pragma unroll
                for (int c = 0; c < 14; c++)
                    acc[c] += k0 * xv[c] + k1 * xv[c + 1] + k2 * xv[c + 2]
                            + k3 * xv[c + 3] + k4 * xv[c + 4];
            }
        }
    }

    // epilogue: transpose rows into smem, pool 2x2, relu, store permuted [p][oc]
    __syncthreads();
    float* sP = sIn;   // reuse: [14 rows][14 cols][32 oc] = 6272 floats
    #pragma unroll
    for (int c = 0; c < 14; c++)
        sP[(r * 14 + c) * 32 + lane] = acc[c];
    __syncthreads();

    float* out = g_h2 + (long)b * 3136;
    for (int i = tid; i < 1568; i += 448) {
        int oc = i & 31; int p = i >> 5;   // p in 0..48
        int pi = p / 7, pj = p - pi * 7;
        int r0 = 2 * pi, c0 = 2 * pj;
        float m = fmaxf(fmaxf(sP[(r0 * 14 + c0) * 32 + oc],
                              sP[(r0 * 14 + c0 + 1) * 32 + oc]),
                        fmaxf(sP[((r0 + 1) * 14 + c0) * 32 + oc],
                              sP[((r0 + 1) * 14 + c0 + 1) * 32 + oc]));
        m += b2[ocBase + oc];
        out[p * 64 + ocBase + oc] = fmaxf(m, 0.f);
    }
}

// ---------------- FC1: (4096,3136) @ (128,3136)^T + bias, relu ----------------
__global__ __launch_bounds__(256) void fc1_kernel(const float* __restrict__ bias) {
    __shared__ float sA[16][68];
    __shared__ float sW[16][68];
    int tid = threadIdx.x;
    int tx = tid & 15;
    int ty = tid >> 4;
    int mBase = blockIdx.x * 64;
    int nBase = blockIdx.y * 64;

    int lrow = tid >> 2;
    int lk   = (tid & 3) * 4;

    const float* A = g_h2;
    const float* w = g_fc1wP;
    float acc[4][4];
    #pragma unroll
    for (int i = 0; i < 4; i++)
        #pragma unroll
        for (int j = 0; j < 4; j++) acc[i][j] = 0.f;

    for (int kt = 0; kt < 3136; kt += 16) {
        float4 a4 = *(const float4*)&A[(long)(mBase + lrow) * 3136 + kt + lk];
        float4 w4 = *(const float4*)&w[(long)(nBase + lrow) * 3136 + kt + lk];
        float av[4] = {a4.x, a4.y, a4.z, a4.w};
        float wv[4] = {w4.x, w4.y, w4.z, w4.w};
        #pragma unroll
        for (int q = 0; q < 4; q++) {
            sA[lk + q][lrow] = av[q];
            sW[lk + q][lrow] = wv[q];
        }
        __syncthreads();
        #pragma unroll
        for (int kk = 0; kk < 16; kk++) {
            float4 a = *(const float4*)&sA[kk][ty * 4];
            float4 bb = *(const float4*)&sW[kk][tx * 4];
            float ar[4] = {a.x, a.y, a.z, a.w};
            float br[4] = {bb.x, bb.y, bb.z, bb.w};
            #pragma unroll
            for (int i = 0; i < 4; i++)
                #pragma unroll
                for (int j = 0; j < 4; j++)
                    acc[i][j] += ar[i] * br[j];
        }
        __syncthreads();
    }

    #pragma unroll
    for (int i = 0; i < 4; i++) {
        int m = mBase + ty * 4 + i;
        #pragma unroll
        for (int j = 0; j < 4; j++) {
            int n = nBase + tx * 4 + j;
            float v = acc[i][j] + bias[n];
            g_f1[(long)m * 128 + n] = fmaxf(v, 0.f);
        }
    }
}

// ---------------- FC2: (4096,128) @ (10,128)^T + bias ----------------
__global__ __launch_bounds__(256) void fc2_kernel(const float* __restrict__ w,
                                                  const float* __restrict__ bias,
                                                  float* __restrict__ out) {
    int idx = blockIdx.x * 256 + threadIdx.x;
    if (idx >= 4096 * 10) return;
    int b = idx / 10, n = idx - b * 10;
    const float* h  = g_f1 + (long)b * 128;
    const float* wr = w + n * 128;
    float s = bias[n];
    #pragma unroll 8
    for (int k = 0; k < 128; k++) s += h[k] * wr[k];
    out[idx] = s;
}

// ---------------- launcher ----------------
extern "C" void kernel_launch(void* const* d_in, const int* in_sizes, int n_in,
                              void* d_out, int out_size) {
    const float* x     = (const float*)d_in[0];
    const float* w1    = (const float*)d_in[1];
    const float* p1    = (const float*)d_in[2];
    const float* b1    = (const float*)d_in[3];
    const float* w2    = (const float*)d_in[4];
    const float* p2    = (const float*)d_in[5];
    const float* b2    = (const float*)d_in[6];
    const float* fc1w  = (const float*)d_in[7];
    const float* fc1b  = (const float*)d_in[8];
    const float* fc2w  = (const float*)d_in[9];
    const float* fc2b  = (const float*)d_in[10];
    float* out = (float*)d_out;

    build_k1_dense<<<4, 256>>>(w1, p1);
    build_k2_dense<<<200, 256>>>(w2, p2);
    permute_fc1w<<<(128 * 3136 + 255) / 256, 256>>>(fc1w);
    conv1_kernel<<<4096, 448>>>(x, b1);

    static const int conv2_smem = (11520 + 2 * 6400) * 4;   // 97280 B
    cudaFuncSetAttribute(conv2_kernel, cudaFuncAttributeMaxDynamicSharedMemorySize, conv2_smem);
    conv2_kernel<<<dim3(4096, 2), 448, conv2_smem>>>(b2);

    fc1_kernel<<<dim3(64, 2), 256>>>(fc1b);
    fc2_kernel<<<160, 256>>>(fc2w, fc2b, out);
}

// round 5
// speedup vs baseline: 2.5861x; 2.2127x over previous
#include <cuda_runtime.h>
#include <cuda_bf16.h>
#include <math.h>
#include <stdint.h>

// ================= scratch (device globals: allocation-free) =================
__device__ float g_K1T[25 * 32];                 // conv1 kernel [tap][oc]
__device__ __nv_bfloat16 g_Bh[51200];            // conv2 W hi, HMMA fragment layout
__device__ __nv_bfloat16 g_Bl[51200];            // conv2 W lo
__device__ short g_tab[832];                     // im2col offset table k -> smem offset
__device__ float g_h1[4096 * 196 * 32];          // conv1 out pos-major [b][pos][ic]
__device__ float g_h2[4096 * 49 * 64];           // conv2 out pos-major [b][pos][oc]
__device__ float g_f1[4096 * 128];
__device__ float g_fc1wP[128 * 3136];            // fc1 W permuted [n][pos*64+oc]

// ================= helpers =================
__device__ __forceinline__ uint32_t smem_u32(const void* p) {
    return (uint32_t)__cvta_generic_to_shared(p);
}
#define CP_ASYNC16(dst_u32, src_ptr) \
    asm volatile("cp.async.cg.shared.global [%0], [%1], 16;" :: "r"(dst_u32), "l"(src_ptr))
#define CP_COMMIT() asm volatile("cp.async.commit_group;")
#define CP_WAIT0() asm volatile("cp.async.wait_group 0;" ::: "memory")

__device__ __forceinline__ void mma_bf16(float* c, uint32_t a0, uint32_t a1,
                                         uint32_t a2, uint32_t a3,
                                         uint32_t b0, uint32_t b1) {
    asm volatile(
        "mma.sync.aligned.m16n8k16.row.col.f32.bf16.bf16.f32 "
        "{%0,%1,%2,%3}, {%4,%5,%6,%7}, {%8,%9}, {%0,%1,%2,%3};"
        : "+f"(c[0]), "+f"(c[1]), "+f"(c[2]), "+f"(c[3])
        : "r"(a0), "r"(a1), "r"(a2), "r"(a3), "r"(b0), "r"(b1));
}

// pack (a,b) -> bf16x2 hi word + exact residual bf16x2 lo word
__device__ __forceinline__ void pack_pair(float a, float b, uint32_t& h, uint32_t& l) {
    __nv_bfloat162 hp = __floats2bfloat162_rn(a, b);    // x=a (low), y=b (high)
    uint32_t hu = *(uint32_t*)&hp;
    float ra = a - __uint_as_float(hu << 16);
    float rb = b - __uint_as_float(hu & 0xFFFF0000u);
    __nv_bfloat162 lp = __floats2bfloat162_rn(ra, rb);
    h = hu;
    l = *(uint32_t*)&lp;
}

// ================= DCLS dense-kernel builders =================
__global__ void build_k1_dense(const float* __restrict__ w1, const float* __restrict__ p1) {
    int t = blockIdx.x * 256 + threadIdx.x;
    if (t >= 32 * 25) return;
    int co = t / 25; int cell = t - co * 25;
    int ii = cell / 5, jj = cell - ii * 5;
    float s = 0.f;
    #pragma unroll 4
    for (int kc = 0; kc < 16; kc++) {
        int e = co * 16 + kc;
        float w  = w1[e];
        float pa = fminf(fmaxf(p1[e],       -2.f), 2.f) + 2.f;
        float pb = fminf(fmaxf(p1[512 + e], -2.f), 2.f) + 2.f;
        int i1 = (int)floorf(pa), i2 = (int)floorf(pb);
        float r1 = pa - (float)i1, r2 = pb - (float)i2;
        if (i1     == ii && i2     == jj) s += w * (1.f - r1) * (1.f - r2);
        if (i1 + 1 == ii && i2     == jj) s += w * r1 * (1.f - r2);
        if (i1     == ii && i2 + 1 == jj) s += w * (1.f - r1) * r2;
        if (i1 + 1 == ii && i2 + 1 == jj) s += w * r1 * r2;
    }
    g_K1T[cell * 32 + co] = s;
}

// conv2 dense DCLS weight -> bf16 hi/lo in HMMA B-fragment layout:
// word w = ((kstep*8 + n8)*2 + reg)*32 + lane, halves = k parity.
// b0(reg0): k_local = 2*(lane%4)+{0,1}, n = n8*8 + lane>>2; b1(reg1): k_local+8.
__global__ void build_k2_frag(const float* __restrict__ w2, const float* __restrict__ p2) {
    int t = blockIdx.x * 256 + threadIdx.x;
    if (t >= 800 * 64) return;
    int k  = t >> 6;        // 0..799
    int oc = t & 63;
    int ci = k / 25; int cell = k - ci * 25;
    int ii = cell / 5, jj = cell - ii * 5;
    float s = 0.f;
    #pragma unroll 4
    for (int kc = 0; kc < 32; kc++) {
        int e = oc * 1024 + ci * 32 + kc;
        float w  = w2[e];
        float pa = fminf(fmaxf(p2[e],         -2.f), 2.f) + 2.f;
        float pb = fminf(fmaxf(p2[65536 + e], -2.f), 2.f) + 2.f;
        int i1 = (int)floorf(pa), i2 = (int)floorf(pb);
        float r1 = pa - (float)i1, r2 = pb - (float)i2;
        if (i1     == ii && i2     == jj) s += w * (1.f - r1) * (1.f - r2);
        if (i1 + 1 == ii && i2     == jj) s += w * r1 * (1.f - r2);
        if (i1     == ii && i2 + 1 == jj) s += w * (1.f - r1) * r2;
        if (i1 + 1 == ii && i2 + 1 == jj) s += w * r1 * r2;
    }
    __nv_bfloat16 hi = __float2bfloat16(s);
    __nv_bfloat16 lo = __float2bfloat16(s - __bfloat162float(hi));
    int ts = k >> 4, kk = k & 15;
    int reg = kk >> 3;
    int ln  = ((kk >> 1) & 3) + (oc & 7) * 4;
    int half = kk & 1;
    int n8 = oc >> 3;
    int w = ((ts * 8 + n8) * 2 + reg) * 32 + ln;
    g_Bh[2 * w + half] = hi;
    g_Bl[2 * w + half] = lo;
}

// im2col offset table: k -> (ky*18+kx)*33 + ic
__global__ void build_tab() {
    int k = blockIdx.x * 256 + threadIdx.x;
    if (k >= 832) return;
    short off = 0;
    if (k < 800) {
        int ic = k / 25; int tap = k - ic * 25;
        int ky = tap / 5, kx = tap - ky * 5;
        off = (short)((ky * 18 + kx) * 33 + ic);
    }
    g_tab[k] = off;
}

// ================= fc1 weight permute =================
__global__ void permute_fc1w(const float* __restrict__ w) {
    int idx = blockIdx.x * 256 + threadIdx.x;
    if (idx >= 128 * 3136) return;
    int n = idx / 3136; int j = idx - n * 3136;
    int p = j >> 6, oc = j & 63;
    g_fc1wP[idx] = w[n * 3136 + oc * 49 + p];
}

// ================= conv1 (1->32, 5x5, pad2) + relu + pool =================
__global__ __launch_bounds__(448, 2) void conv1_kernel(const float* __restrict__ x,
                                                       const float* __restrict__ b1) {
    __shared__ float sImg[32][32];
    __shared__ float sK[800];
    int b = blockIdx.x;
    int tid = threadIdx.x;
    int lane = tid & 31;
    int t = tid >> 5;

    for (int i = tid; i < 1024; i += 448) ((float*)sImg)[i] = 0.f;
    for (int i = tid; i < 800;  i += 448) sK[i] = g_K1T[i];
    __syncthreads();
    const float* xb = x + (long)b * 784;
    for (int i = tid; i < 784; i += 448) {
        int r = i / 28, c = i - r * 28;
        sImg[r + 2][c + 2] = xb[i];
    }
    __syncthreads();

    float pr[14];
    #pragma unroll
    for (int rowSel = 0; rowSel < 2; rowSel++) {
        int r = 2 * t + rowSel;
        float acc[28];
        #pragma unroll
        for (int c = 0; c < 28; c++) acc[c] = 0.f;
        #pragma unroll
        for (int ky = 0; ky < 5; ky++) {
            const float* xr = &sImg[r + ky][0];
            float xv[32];
            #pragma unroll
            for (int q = 0; q < 8; q++)
                *(float4*)&xv[q * 4] = *(const float4*)&xr[q * 4];
            const float* kp = &sK[(ky * 5) * 32 + lane];
            float k0 = kp[0], k1 = kp[32], k2 = kp[64], k3 = kp[96], k4 = kp[128];
            #pragma unroll
            for (int c = 0; c < 28; c++)
                acc[c] += k0 * xv[c] + k1 * xv[c + 1] + k2 * xv[c + 2]
                        + k3 * xv[c + 3] + k4 * xv[c + 4];
        }
        #pragma unroll
        for (int j = 0; j < 14; j++) {
            float m = fmaxf(acc[2 * j], acc[2 * j + 1]);
            pr[j] = rowSel ? fmaxf(pr[j], m) : m;
        }
    }

    float bias = b1[lane];
    float* out = g_h1 + (long)b * 6272;
    #pragma unroll
    for (int j = 0; j < 14; j++)
        out[(t * 14 + j) * 32 + lane] = fmaxf(pr[j] + bias, 0.f);
}

// ================= conv2: bf16-split HMMA implicit GEMM =================
// CTA = image; 416 threads = 13 warps; warp = 16-row M tile (196 valid of 208).
// D[208x64] = A[208x800] * B[64x800]^T via mma.sync m16n8k16, 3-term bf16 split.
// smem floats: sImg[10692] | sTab 416 u32 | Bbuf 2x5120 u32.  total 21348 f = 85392 B.
#define C2_SMEM_BYTES (21348 * 4)

__global__ __launch_bounds__(416, 2) void conv2_kernel(const float* __restrict__ b2) {
    extern __shared__ float sm[];
    float* sImg = sm;                               // 10692
    uint32_t* sTab32 = (uint32_t*)(sm + 10692);     // 416
    uint32_t* Bbuf = (uint32_t*)(sm + 11108);       // 2 x 5120

    int b = blockIdx.x;
    int tid = threadIdx.x;
    int lane = tid & 31;
    int warp = tid >> 5;    // 0..12

    // prefetch B chunk 0 (5 ksteps: hi 10240B + lo 10240B)
    {
        uint32_t dst = smem_u32(Bbuf);
        const char* sh = (const char*)g_Bh;
        const char* sl = (const char*)g_Bl;
        for (int i = tid; i < 640; i += 416) CP_ASYNC16(dst + i * 16, sh + i * 16);
        for (int i = tid; i < 640; i += 416) CP_ASYNC16(dst + 10240 + i * 16, sl + i * 16);
        CP_COMMIT();
    }

    // stage image (18x18 halo grid, [cell][ic] stride 33) + offset table
    for (int i = tid; i < 10692; i += 416) sImg[i] = 0.f;
    {
        const uint32_t* gt = (const uint32_t*)g_tab;
        for (int i = tid; i < 416; i += 416) sTab32[i] = gt[i];
    }
    __syncthreads();
    {
        const float* hb = g_h1 + (long)b * 6272;
        for (int i = tid; i < 6272; i += 416) {
            int ic = i & 31; int p = i >> 5;
            int rr = p / 14, cc = p - rr * 14;
            sImg[((rr + 2) * 18 + (cc + 2)) * 33 + ic] = hb[i];
        }
    }
    __syncthreads();

    // per-thread fragment coordinates
    int m0 = warp * 16 + (lane >> 2);
    int m1 = m0 + 8;
    bool vr0 = m0 < 196, vr1 = m1 < 196;
    int pr0 = m0 / 14, pc0 = m0 - pr0 * 14;
    int pr1 = m1 / 14, pc1 = m1 - pr1 * 14;
    int base0 = (pr0 * 18 + pc0) * 33;
    int base1 = (pr1 * 18 + pc1) * 33;
    int kq = 2 * (lane & 3);

    float acc[8][4];
    #pragma unroll
    for (int i = 0; i < 8; i++)
        #pragma unroll
        for (int j = 0; j < 4; j++) acc[i][j] = 0.f;

    for (int c = 0; c < 10; c++) {
        CP_WAIT0();
        __syncthreads();            // chunk c data visible; chunk c-1 compute retired
        if (c < 9) {
            uint32_t dst = smem_u32(Bbuf + ((c + 1) & 1) * 5120);
            const char* sh = (const char*)g_Bh + (c + 1) * 10240;
            const char* sl = (const char*)g_Bl + (c + 1) * 10240;
            for (int i = tid; i < 640; i += 416) CP_ASYNC16(dst + i * 16, sh + i * 16);
            for (int i = tid; i < 640; i += 416) CP_ASYNC16(dst + 10240 + i * 16, sl + i * 16);
            CP_COMMIT();
        }
        const uint32_t* Bc = Bbuf + (c & 1) * 5120 + lane;

        #pragma unroll
        for (int tp = 0; tp < 5; tp++) {
            int k0 = (c * 5 + tp) * 16 + kq;
            uint32_t t01 = sTab32[k0 >> 1];
            uint32_t t89 = sTab32[(k0 >> 1) + 4];
            int o0 = (int)(short)(t01 & 0xFFFF), o1 = (int)(short)(t01 >> 16);
            int o8 = (int)(short)(t89 & 0xFFFF), o9 = (int)(short)(t89 >> 16);
            float v00 = vr0 ? sImg[base0 + o0] : 0.f;
            float v01 = vr0 ? sImg[base0 + o1] : 0.f;
            float v08 = vr0 ? sImg[base0 + o8] : 0.f;
            float v09 = vr0 ? sImg[base0 + o9] : 0.f;
            float v10 = vr1 ? sImg[base1 + o0] : 0.f;
            float v11 = vr1 ? sImg[base1 + o1] : 0.f;
            float v18 = vr1 ? sImg[base1 + o8] : 0.f;
            float v19 = vr1 ? sImg[base1 + o9] : 0.f;

            uint32_t ah0, ah1, ah2, ah3, al0, al1, al2, al3;
            pack_pair(v00, v01, ah0, al0);
            pack_pair(v10, v11, ah1, al1);
            pack_pair(v08, v09, ah2, al2);
            pack_pair(v18, v19, ah3, al3);

            const uint32_t* bp = Bc + tp * 512;
            #pragma unroll
            for (int n8 = 0; n8 < 8; n8++) {
                uint32_t bh0 = bp[(n8 * 2 + 0) * 32];
                uint32_t bh1 = bp[(n8 * 2 + 1) * 32];
                uint32_t bl0 = bp[2560 + (n8 * 2 + 0) * 32];
                uint32_t bl1 = bp[2560 + (n8 * 2 + 1) * 32];
                mma_bf16(acc[n8], ah0, ah1, ah2, ah3, bh0, bh1);
                mma_bf16(acc[n8], ah0, ah1, ah2, ah3, bl0, bl1);
                mma_bf16(acc[n8], al0, al1, al2, al3, bh0, bh1);
            }
        }
    }

    // epilogue: acc -> smem (reuse), 2x2 pool + bias + relu, store [pos][oc]
    __syncthreads();
    float* pool = sm;     // 196 rows x 66 = 12936 floats
    #pragma unroll
    for (int n8 = 0; n8 < 8; n8++) {
        int col = n8 * 8 + kq;
        if (vr0) { pool[m0 * 66 + col] = acc[n8][0]; pool[m0 * 66 + col + 1] = acc[n8][1]; }
        if (vr1) { pool[m1 * 66 + col] = acc[n8][2]; pool[m1 * 66 + col + 1] = acc[n8][3]; }
    }
    __syncthreads();
    float* out = g_h2 + (long)b * 3136;
    for (int i = tid; i < 3136; i += 416) {
        int oc = i & 63; int pp = i >> 6;
        int pr = pp / 7, pc = pp - pr * 7;
        int ma = (2 * pr) * 14 + 2 * pc;
        float v = fmaxf(fmaxf(pool[ma * 66 + oc],        pool[(ma + 1) * 66 + oc]),
                        fmaxf(pool[(ma + 14) * 66 + oc], pool[(ma + 15) * 66 + oc]));
        out[i] = fmaxf(v + b2[oc], 0.f);
    }
}

// ================= FC1 =================
__global__ __launch_bounds__(256) void fc1_kernel(const float* __restrict__ bias) {
    __shared__ float sA[16][68];
    __shared__ float sW[16][68];
    int tid = threadIdx.x;
    int tx = tid & 15;
    int ty = tid >> 4;
    int mBase = blockIdx.x * 64;
    int nBase = blockIdx.y * 64;

    int lrow = tid >> 2;
    int lk   = (tid & 3) * 4;

    const float* A = g_h2;
    const float* w = g_fc1wP;
    float acc[4][4];
    #pragma unroll
    for (int i = 0; i < 4; i++)
        #pragma unroll
        for (int j = 0; j < 4; j++) acc[i][j] = 0.f;

    for (int kt = 0; kt < 3136; kt += 16) {
        float4 a4 = *(const float4*)&A[(long)(mBase + lrow) * 3136 + kt + lk];
        float4 w4 = *(const float4*)&w[(long)(nBase + lrow) * 3136 + kt + lk];
        float av[4] = {a4.x, a4.y, a4.z, a4.w};
        float wv[4] = {w4.x, w4.y, w4.z, w4.w};
        #pragma unroll
        for (int q = 0; q < 4; q++) {
            sA[lk + q][lrow] = av[q];
            sW[lk + q][lrow] = wv[q];
        }
        __syncthreads();
        #pragma unroll
        for (int kk = 0; kk < 16; kk++) {
            float4 a = *(const float4*)&sA[kk][ty * 4];
            float4 bb = *(const float4*)&sW[kk][tx * 4];
            float ar[4] = {a.x, a.y, a.z, a.w};
            float br[4] = {bb.x, bb.y, bb.z, bb.w};
            #pragma unroll
            for (int i = 0; i < 4; i++)
                #pragma unroll
                for (int j = 0; j < 4; j++)
                    acc[i][j] += ar[i] * br[j];
        }
        __syncthreads();
    }

    #pragma unroll
    for (int i = 0; i < 4; i++) {
        int m = mBase + ty * 4 + i;
        #pragma unroll
        for (int j = 0; j < 4; j++) {
            int n = nBase + tx * 4 + j;
            float v = acc[i][j] + bias[n];
            g_f1[(long)m * 128 + n] = fmaxf(v, 0.f);
        }
    }
}

// ================= FC2 =================
__global__ __launch_bounds__(256) void fc2_kernel(const float* __restrict__ w,
                                                  const float* __restrict__ bias,
                                                  float* __restrict__ out) {
    int idx = blockIdx.x * 256 + threadIdx.x;
    if (idx >= 4096 * 10) return;
    int b = idx / 10, n = idx - b * 10;
    const float* h  = g_f1 + (long)b * 128;
    const float* wr = w + n * 128;
    float s = bias[n];
    #pragma unroll 8
    for (int k = 0; k < 128; k++) s += h[k] * wr[k];
    out[idx] = s;
}

// ================= launcher =================
extern "C" void kernel_launch(void* const* d_in, const int* in_sizes, int n_in,
                              void* d_out, int out_size) {
    const float* x     = (const float*)d_in[0];
    const float* w1    = (const float*)d_in[1];
    const float* p1    = (const float*)d_in[2];
    const float* b1    = (const float*)d_in[3];
    const float* w2    = (const float*)d_in[4];
    const float* p2    = (const float*)d_in[5];
    const float* b2    = (const float*)d_in[6];
    const float* fc1w  = (const float*)d_in[7];
    const float* fc1b  = (const float*)d_in[8];
    const float* fc2w  = (const float*)d_in[9];
    const float* fc2b  = (const float*)d_in[10];
    float* out = (float*)d_out;

    build_k1_dense<<<4, 256>>>(w1, p1);
    build_k2_frag<<<200, 256>>>(w2, p2);
    build_tab<<<4, 256>>>();
    permute_fc1w<<<(128 * 3136 + 255) / 256, 256>>>(fc1w);
    conv1_kernel<<<4096, 448>>>(x, b1);

    cudaFuncSetAttribute(conv2_kernel, cudaFuncAttributeMaxDynamicSharedMemorySize, C2_SMEM_BYTES);
    conv2_kernel<<<4096, 416, C2_SMEM_BYTES>>>(b2);

    fc1_kernel<<<dim3(64, 2), 256>>>(fc1b);
    fc2_kernel<<<160, 256>>>(fc2w, fc2b, out);
}

// round 6
// speedup vs baseline: 2.9919x; 1.1569x over previous
#include <cuda_runtime.h>
#include <cuda_bf16.h>
#include <math.h>
#include <stdint.h>

// ================= scratch (device globals: allocation-free) =================
__device__ float g_K1T[25 * 32];                 // conv1 kernel [tap][oc]
__device__ __nv_bfloat16 g_Bh[64000];            // conv2 W hi, frag layout, lane-stride 20 words
__device__ __nv_bfloat16 g_Bl[64000];            // conv2 W lo
__device__ __nv_bfloat16 g_W1h[409600];          // fc1 W hi, frag layout
__device__ __nv_bfloat16 g_W1l[409600];          // fc1 W lo
__device__ short g_tab[832];                     // im2col offset table k -> smem offset
__device__ float g_h1[4096 * 196 * 32];          // conv1 out pos-major [b][pos][ic]
__device__ __nv_bfloat16 g_Ah[4096 * 3200];      // conv2 out hi (fc1 A), K padded to 3200 (pad=0)
__device__ __nv_bfloat16 g_Al[4096 * 3200];      // conv2 out lo
__device__ float g_f1[4096 * 128];               // fc1 output

// ================= helpers =================
__device__ __forceinline__ uint32_t smem_u32(const void* p) {
    return (uint32_t)__cvta_generic_to_shared(p);
}
#define CP_ASYNC16(dst_u32, src_ptr) \
    asm volatile("cp.async.cg.shared.global [%0], [%1], 16;" :: "r"(dst_u32), "l"(src_ptr))
#define CP_COMMIT() asm volatile("cp.async.commit_group;")
#define CP_WAIT0() asm volatile("cp.async.wait_group 0;" ::: "memory")

__device__ __forceinline__ void mma_bf16(float* c, uint32_t a0, uint32_t a1,
                                         uint32_t a2, uint32_t a3,
                                         uint32_t b0, uint32_t b1) {
    asm volatile(
        "mma.sync.aligned.m16n8k16.row.col.f32.bf16.bf16.f32 "
        "{%0,%1,%2,%3}, {%4,%5,%6,%7}, {%8,%9}, {%0,%1,%2,%3};"
        : "+f"(c[0]), "+f"(c[1]), "+f"(c[2]), "+f"(c[3])
        : "r"(a0), "r"(a1), "r"(a2), "r"(a3), "r"(b0), "r"(b1));
}

__device__ __forceinline__ void pack_pair(float a, float b, uint32_t& h, uint32_t& l) {
    __nv_bfloat162 hp = __floats2bfloat162_rn(a, b);
    uint32_t hu = *(uint32_t*)&hp;
    float ra = a - __uint_as_float(hu << 16);
    float rb = b - __uint_as_float(hu & 0xFFFF0000u);
    __nv_bfloat162 lp = __floats2bfloat162_rn(ra, rb);
    h = hu;
    l = *(uint32_t*)&lp;
}

// ================= DCLS dense-kernel builders =================
__global__ void build_k1_dense(const float* __restrict__ w1, const float* __restrict__ p1) {
    int t = blockIdx.x * 256 + threadIdx.x;
    if (t >= 32 * 25) return;
    int co = t / 25; int cell = t - co * 25;
    int ii = cell / 5, jj = cell - ii * 5;
    float s = 0.f;
    #pragma unroll 4
    for (int kc = 0; kc < 16; kc++) {
        int e = co * 16 + kc;
        float w  = w1[e];
        float pa = fminf(fmaxf(p1[e],       -2.f), 2.f) + 2.f;
        float pb = fminf(fmaxf(p1[512 + e], -2.f), 2.f) + 2.f;
        int i1 = (int)floorf(pa), i2 = (int)floorf(pb);
        float r1 = pa - (float)i1, r2 = pb - (float)i2;
        if (i1     == ii && i2     == jj) s += w * (1.f - r1) * (1.f - r2);
        if (i1 + 1 == ii && i2     == jj) s += w * r1 * (1.f - r2);
        if (i1     == ii && i2 + 1 == jj) s += w * (1.f - r1) * r2;
        if (i1 + 1 == ii && i2 + 1 == jj) s += w * r1 * r2;
    }
    g_K1T[cell * 32 + co] = s;
}

// conv2 W -> bf16 hi/lo, frag layout: chunk c(5 ksteps): word = c*3200 + (tp*32+ln)*20 + n8*2 + reg
__global__ void build_k2_frag(const float* __restrict__ w2, const float* __restrict__ p2) {
    int t = blockIdx.x * 256 + threadIdx.x;
    if (t >= 800 * 64) return;
    int k  = t >> 6;        // 0..799
    int oc = t & 63;
    int ci = k / 25; int cell = k - ci * 25;
    int ii = cell / 5, jj = cell - ii * 5;
    float s = 0.f;
    #pragma unroll 4
    for (int kc = 0; kc < 32; kc++) {
        int e = oc * 1024 + ci * 32 + kc;
        float w  = w2[e];
        float pa = fminf(fmaxf(p2[e],         -2.f), 2.f) + 2.f;
        float pb = fminf(fmaxf(p2[65536 + e], -2.f), 2.f) + 2.f;
        int i1 = (int)floorf(pa), i2 = (int)floorf(pb);
        float r1 = pa - (float)i1, r2 = pb - (float)i2;
        if (i1     == ii && i2     == jj) s += w * (1.f - r1) * (1.f - r2);
        if (i1 + 1 == ii && i2     == jj) s += w * r1 * (1.f - r2);
        if (i1     == ii && i2 + 1 == jj) s += w * (1.f - r1) * r2;
        if (i1 + 1 == ii && i2 + 1 == jj) s += w * r1 * r2;
    }
    __nv_bfloat16 hi = __float2bfloat16(s);
    __nv_bfloat16 lo = __float2bfloat16(s - __bfloat162float(hi));
    int ts = k >> 4, kk = k & 15;
    int reg = kk >> 3, half = kk & 1;
    int ln  = ((kk >> 1) & 3) + (oc & 7) * 4;
    int n8  = oc >> 3;
    int c   = ts / 5, tp = ts - c * 5;
    int w = c * 3200 + (tp * 32 + ln) * 20 + n8 * 2 + reg;
    g_Bh[2 * w + half] = hi;
    g_Bl[2 * w + half] = lo;
}

// fc1 W -> bf16 hi/lo, frag layout: word = ((ts*4+nq)*32+ln)*8 + n8l*2 + reg
__global__ void build_w1_frag(const float* __restrict__ w) {
    int t = blockIdx.x * 256 + threadIdx.x;
    if (t >= 128 * 3200) return;
    int n = t / 3200; int k = t - n * 3200;
    float v = 0.f;
    if (k < 3136) {
        int p = k >> 6, oc = k & 63;
        v = w[n * 3136 + oc * 49 + p];
    }
    __nv_bfloat16 hi = __float2bfloat16(v);
    __nv_bfloat16 lo = __float2bfloat16(v - __bfloat162float(hi));
    int ts = k >> 4, kk = k & 15;
    int reg = kk >> 3, half = kk & 1;
    int ln  = ((kk >> 1) & 3) + (n & 7) * 4;
    int n8  = n >> 3;
    int nq = n8 >> 2, n8l = n8 & 3;
    int word = ((ts * 4 + nq) * 32 + ln) * 8 + n8l * 2 + reg;
    g_W1h[2 * word + half] = hi;
    g_W1l[2 * word + half] = lo;
}

__global__ void build_tab() {
    int k = blockIdx.x * 256 + threadIdx.x;
    if (k >= 832) return;
    short off = 0;
    if (k < 800) {
        int ic = k / 25; int tap = k - ic * 25;
        int ky = tap / 5, kx = tap - ky * 5;
        off = (short)((ky * 18 + kx) * 33 + ic);
    }
    g_tab[k] = off;
}

// ================= conv1 (1->32, 5x5, pad2) + relu + pool =================
__global__ __launch_bounds__(448, 2) void conv1_kernel(const float* __restrict__ x,
                                                       const float* __restrict__ b1) {
    __shared__ float sImg[32][32];
    __shared__ float sK[800];
    int b = blockIdx.x;
    int tid = threadIdx.x;
    int lane = tid & 31;
    int t = tid >> 5;

    for (int i = tid; i < 1024; i += 448) ((float*)sImg)[i] = 0.f;
    for (int i = tid; i < 800;  i += 448) sK[i] = g_K1T[i];
    __syncthreads();
    const float* xb = x + (long)b * 784;
    for (int i = tid; i < 784; i += 448) {
        int r = i / 28, c = i - r * 28;
        sImg[r + 2][c + 2] = xb[i];
    }
    __syncthreads();

    float pr[14];
    #pragma unroll
    for (int rowSel = 0; rowSel < 2; rowSel++) {
        int r = 2 * t + rowSel;
        float acc[28];
        #pragma unroll
        for (int c = 0; c < 28; c++) acc[c] = 0.f;
        #pragma unroll
        for (int ky = 0; ky < 5; ky++) {
            const float* xr = &sImg[r + ky][0];
            float xv[32];
            #pragma unroll
            for (int q = 0; q < 8; q++)
                *(float4*)&xv[q * 4] = *(const float4*)&xr[q * 4];
            const float* kp = &sK[(ky * 5) * 32 + lane];
            float k0 = kp[0], k1 = kp[32], k2 = kp[64], k3 = kp[96], k4 = kp[128];
            #pragma unroll
            for (int c = 0; c < 28; c++)
                acc[c] += k0 * xv[c] + k1 * xv[c + 1] + k2 * xv[c + 2]
                        + k3 * xv[c + 3] + k4 * xv[c + 4];
        }
        #pragma unroll
        for (int j = 0; j < 14; j++) {
            float m = fmaxf(acc[2 * j], acc[2 * j + 1]);
            pr[j] = rowSel ? fmaxf(pr[j], m) : m;
        }
    }

    float bias = b1[lane];
    float* out = g_h1 + (long)b * 6272;
    #pragma unroll
    for (int j = 0; j < 14; j++)
        out[(t * 14 + j) * 32 + lane] = fmaxf(pr[j] + bias, 0.f);
}

// ================= conv2: bf16-split HMMA implicit GEMM =================
// CTA = image; 416 threads = 13 warps; warp = 16-row M tile (196 valid of 208).
// smem floats: sImg 10692 | sTab 416 | Bbuf 12800 (2 bufs x (hi 3200 + lo 3200) words)
#define C2_SMEM_BYTES (23908 * 4)

__global__ __launch_bounds__(416, 2) void conv2_kernel(const float* __restrict__ b2) {
    extern __shared__ float sm[];
    float* sImg = sm;                               // 10692
    uint32_t* sTab32 = (uint32_t*)(sm + 10692);     // 416
    uint32_t* Bbuf = (uint32_t*)(sm + 11108);       // 12800 words

    int b = blockIdx.x;
    int tid = threadIdx.x;
    int lane = tid & 31;
    int warp = tid >> 5;    // 0..12

    uint32_t BbufA = smem_u32(Bbuf);
    // prefetch B chunk 0 (hi 12800B + lo 12800B)
    for (int i = tid; i < 800; i += 416) {
        CP_ASYNC16(BbufA + i * 16, (const char*)g_Bh + i * 16);
        CP_ASYNC16(BbufA + 12800 + i * 16, (const char*)g_Bl + i * 16);
    }
    CP_COMMIT();

    // stage image (18x18 halo grid, [cell][ic] stride 33) + offset table
    for (int i = tid; i < 10692; i += 416) sImg[i] = 0.f;
    {
        const uint32_t* gt = (const uint32_t*)g_tab;
        if (tid < 416) sTab32[tid] = gt[tid];
    }
    __syncthreads();
    {
        const float* hb = g_h1 + (long)b * 6272;
        for (int i = tid; i < 6272; i += 416) {
            int ic = i & 31; int p = i >> 5;
            int rr = p / 14, cc = p - rr * 14;
            sImg[((rr + 2) * 18 + (cc + 2)) * 33 + ic] = hb[i];
        }
    }
    __syncthreads();

    int m0 = warp * 16 + (lane >> 2);
    int m1 = m0 + 8;
    bool vr0 = m0 < 196, vr1 = m1 < 196;
    int pr0 = m0 / 14, pc0 = m0 - pr0 * 14;
    int pr1 = m1 / 14, pc1 = m1 - pr1 * 14;
    int base0 = (pr0 * 18 + pc0) * 33;
    int base1 = (pr1 * 18 + pc1) * 33;
    int kq = 2 * (lane & 3);

    float acc[8][4];
    #pragma unroll
    for (int i = 0; i < 8; i++)
        #pragma unroll
        for (int j = 0; j < 4; j++) acc[i][j] = 0.f;

    for (int c = 0; c < 10; c++) {
        CP_WAIT0();
        __syncthreads();
        if (c < 9) {
            uint32_t dst = BbufA + ((c + 1) & 1) * 25600;
            const char* sh = (const char*)g_Bh + (c + 1) * 12800;
            const char* sl = (const char*)g_Bl + (c + 1) * 12800;
            for (int i = tid; i < 800; i += 416) {
                CP_ASYNC16(dst + i * 16, sh + i * 16);
                CP_ASYNC16(dst + 12800 + i * 16, sl + i * 16);
            }
            CP_COMMIT();
        }
        const uint32_t* Bc = Bbuf + (c & 1) * 6400;

        #pragma unroll
        for (int tp = 0; tp < 5; tp++) {
            int k0 = (c * 5 + tp) * 16 + kq;
            uint32_t t01 = sTab32[k0 >> 1];
            uint32_t t89 = sTab32[(k0 >> 1) + 4];
            int o0 = (int)(short)(t01 & 0xFFFF), o1 = (int)(short)(t01 >> 16);
            int o8 = (int)(short)(t89 & 0xFFFF), o9 = (int)(short)(t89 >> 16);
            float v00 = vr0 ? sImg[base0 + o0] : 0.f;
            float v01 = vr0 ? sImg[base0 + o1] : 0.f;
            float v08 = vr0 ? sImg[base0 + o8] : 0.f;
            float v09 = vr0 ? sImg[base0 + o9] : 0.f;
            float v10 = vr1 ? sImg[base1 + o0] : 0.f;
            float v11 = vr1 ? sImg[base1 + o1] : 0.f;
            float v18 = vr1 ? sImg[base1 + o8] : 0.f;
            float v19 = vr1 ? sImg[base1 + o9] : 0.f;

            uint32_t ah0, ah1, ah2, ah3, al0, al1, al2, al3;
            pack_pair(v00, v01, ah0, al0);
            pack_pair(v10, v11, ah1, al1);
            pack_pair(v08, v09, ah2, al2);
            pack_pair(v18, v19, ah3, al3);

            const uint32_t* bpH = Bc + (tp * 32 + lane) * 20;
            const uint32_t* bpL = bpH + 3200;
            #pragma unroll
            for (int q = 0; q < 4; q++) {
                uint4 h4 = *(const uint4*)&bpH[q * 4];
                uint4 l4 = *(const uint4*)&bpL[q * 4];
                mma_bf16(acc[2 * q],     ah0, ah1, ah2, ah3, h4.x, h4.y);
                mma_bf16(acc[2 * q],     ah0, ah1, ah2, ah3, l4.x, l4.y);
                mma_bf16(acc[2 * q],     al0, al1, al2, al3, h4.x, h4.y);
                mma_bf16(acc[2 * q + 1], ah0, ah1, ah2, ah3, h4.z, h4.w);
                mma_bf16(acc[2 * q + 1], ah0, ah1, ah2, ah3, l4.z, l4.w);
                mma_bf16(acc[2 * q + 1], al0, al1, al2, al3, h4.z, h4.w);
            }
        }
    }

    // epilogue: acc -> smem, 2x2 pool + bias + relu, split to bf16 hi/lo [b][p*64+oc]
    __syncthreads();
    float* pool = sm;     // 196 x 66
    #pragma unroll
    for (int n8 = 0; n8 < 8; n8++) {
        int col = n8 * 8 + kq;
        if (vr0) { pool[m0 * 66 + col] = acc[n8][0]; pool[m0 * 66 + col + 1] = acc[n8][1]; }
        if (vr1) { pool[m1 * 66 + col] = acc[n8][2]; pool[m1 * 66 + col + 1] = acc[n8][3]; }
    }
    __syncthreads();
    __nv_bfloat16* outH = g_Ah + (long)b * 3200;
    __nv_bfloat16* outL = g_Al + (long)b * 3200;
    for (int i = tid; i < 3136; i += 416) {
        int oc = i & 63; int pp = i >> 6;
        int pr = pp / 7, pc = pp - pr * 7;
        int ma = (2 * pr) * 14 + 2 * pc;
        float v = fmaxf(fmaxf(pool[ma * 66 + oc],        pool[(ma + 1) * 66 + oc]),
                        fmaxf(pool[(ma + 14) * 66 + oc], pool[(ma + 15) * 66 + oc]));
        v = fmaxf(v + b2[oc], 0.f);
        __nv_bfloat16 hi = __float2bfloat16(v);
        __nv_bfloat16 lo = __float2bfloat16(v - __bfloat162float(hi));
        outH[i] = hi;
        outL[i] = lo;
    }
}

// ================= FC1: bf16-split HMMA GEMM (4096x128x3200) =================
// grid 128: CTA = 32 M-rows, full N=128. 256 threads = 8 warps (wm 0..1 x wn 0..3).
// smem words: sA 2 x 2816 (hi 1408 + lo 1408, row stride 44) | sB 2 x 10240 (hi 5120 + lo 5120)
#define FC1_SMEM_BYTES ((5632 + 20480) * 4)

__global__ __launch_bounds__(256, 1) void fc1_kernel(const float* __restrict__ bias) {
    extern __shared__ uint32_t smw[];
    uint32_t* sA = smw;            // 2 x 2816
    uint32_t* sB = smw + 5632;     // 2 x 10240
    int tid = threadIdx.x;
    int lane = tid & 31;
    int warp = tid >> 5;
    int wm = warp & 1, wn = warp >> 1;
    int mBase = blockIdx.x * 32;

    uint32_t sAaddr = smem_u32(sA);
    uint32_t sBaddr = smem_u32(sB);

    // stage chunk 0 into buffer 0
    {
        for (int i = tid; i < 320; i += 256) {
            int row = i / 10, g = i - row * 10;
            long so = ((long)(mBase + row) * 3200) * 2 + g * 16;
            CP_ASYNC16(sAaddr + row * 176 + g * 16, (const char*)g_Ah + so);
            CP_ASYNC16(sAaddr + 5632 + row * 176 + g * 16, (const char*)g_Al + so);
        }
        for (int i = tid; i < 1280; i += 256) {
            CP_ASYNC16(sBaddr + i * 16, (const char*)g_W1h + i * 16);
            CP_ASYNC16(sBaddr + 20480 + i * 16, (const char*)g_W1l + i * 16);
        }
        CP_COMMIT();
    }

    float acc[4][4];
    #pragma unroll
    for (int i = 0; i < 4; i++)
        #pragma unroll
        for (int j = 0; j < 4; j++) acc[i][j] = 0.f;

    int r0w = (wm * 16 + (lane >> 2)) * 44;
    int r1w = r0w + 8 * 44;

    for (int c = 0; c < 40; c++) {
        CP_WAIT0();
        __syncthreads();
        if (c < 39) {
            int p = (c + 1) & 1;
            uint32_t dA = sAaddr + p * 11264;        // 2816 words
            for (int i = tid; i < 320; i += 256) {
                int row = i / 10, g = i - row * 10;
                long so = ((long)(mBase + row) * 3200 + (c + 1) * 80) * 2 + g * 16;
                CP_ASYNC16(dA + row * 176 + g * 16, (const char*)g_Ah + so);
                CP_ASYNC16(dA + 5632 + row * 176 + g * 16, (const char*)g_Al + so);
            }
            uint32_t dB = sBaddr + p * 40960;        // 10240 words
            for (int i = tid; i < 1280; i += 256) {
                CP_ASYNC16(dB + i * 16, (const char*)g_W1h + (c + 1) * 20480 + i * 16);
                CP_ASYNC16(dB + 20480 + i * 16, (const char*)g_W1l + (c + 1) * 20480 + i * 16);
            }
            CP_COMMIT();
        }
        const uint32_t* Ab = sA + (c & 1) * 2816;
        const uint32_t* Bb = sB + (c & 1) * 10240;

        #pragma unroll
        for (int tp = 0; tp < 5; tp++) {
            int aw = tp * 8 + (lane & 3);
            uint32_t ah0 = Ab[r0w + aw],        ah1 = Ab[r1w + aw];
            uint32_t ah2 = Ab[r0w + aw + 4],    ah3 = Ab[r1w + aw + 4];
            uint32_t al0 = Ab[1408 + r0w + aw],     al1 = Ab[1408 + r1w + aw];
            uint32_t al2 = Ab[1408 + r0w + aw + 4], al3 = Ab[1408 + r1w + aw + 4];
            const uint32_t* bpH = Bb + ((tp * 4 + wn) * 32 + lane) * 8;
            const uint32_t* bpL = bpH + 5120;
            uint4 h0 = *(const uint4*)&bpH[0];
            uint4 h1 = *(const uint4*)&bpH[4];
            uint4 l0 = *(const uint4*)&bpL[0];
            uint4 l1 = *(const uint4*)&bpL[4];
            mma_bf16(acc[0], ah0, ah1, ah2, ah3, h0.x, h0.y);
            mma_bf16(acc[0], ah0, ah1, ah2, ah3, l0.x, l0.y);
            mma_bf16(acc[0], al0, al1, al2, al3, h0.x, h0.y);
            mma_bf16(acc[1], ah0, ah1, ah2, ah3, h0.z, h0.w);
            mma_bf16(acc[1], ah0, ah1, ah2, ah3, l0.z, l0.w);
            mma_bf16(acc[1], al0, al1, al2, al3, h0.z, h0.w);
            mma_bf16(acc[2], ah0, ah1, ah2, ah3, h1.x, h1.y);
            mma_bf16(acc[2], ah0, ah1, ah2, ah3, l1.x, l1.y);
            mma_bf16(acc[2], al0, al1, al2, al3, h1.x, h1.y);
            mma_bf16(acc[3], ah0, ah1, ah2, ah3, h1.z, h1.w);
            mma_bf16(acc[3], ah0, ah1, ah2, ah3, l1.z, l1.w);
            mma_bf16(acc[3], al0, al1, al2, al3, h1.z, h1.w);
        }
    }

    int row = wm * 16 + (lane >> 2);
    int m = mBase + row;
    int colb = wn * 32 + 2 * (lane & 3);
    #pragma unroll
    for (int q = 0; q < 4; q++) {
        int n0 = colb + q * 8;
        g_f1[m * 128 + n0]           = fmaxf(acc[q][0] + bias[n0], 0.f);
        g_f1[m * 128 + n0 + 1]       = fmaxf(acc[q][1] + bias[n0 + 1], 0.f);
        g_f1[(m + 8) * 128 + n0]     = fmaxf(acc[q][2] + bias[n0], 0.f);
        g_f1[(m + 8) * 128 + n0 + 1] = fmaxf(acc[q][3] + bias[n0 + 1], 0.f);
    }
}

// ================= FC2 =================
__global__ __launch_bounds__(256) void fc2_kernel(const float* __restrict__ w,
                                                  const float* __restrict__ bias,
                                                  float* __restrict__ out) {
    int idx = blockIdx.x * 256 + threadIdx.x;
    if (idx >= 4096 * 10) return;
    int b = idx / 10, n = idx - b * 10;
    const float* h  = g_f1 + (long)b * 128;
    const float* wr = w + n * 128;
    float s = bias[n];
    #pragma unroll 8
    for (int k = 0; k < 128; k++) s += h[k] * wr[k];
    out[idx] = s;
}

// ================= launcher =================
extern "C" void kernel_launch(void* const* d_in, const int* in_sizes, int n_in,
                              void* d_out, int out_size) {
    const float* x     = (const float*)d_in[0];
    const float* w1    = (const float*)d_in[1];
    const float* p1    = (const float*)d_in[2];
    const float* b1    = (const float*)d_in[3];
    const float* w2    = (const float*)d_in[4];
    const float* p2    = (const float*)d_in[5];
    const float* b2    = (const float*)d_in[6];
    const float* fc1w  = (const float*)d_in[7];
    const float* fc1b  = (const float*)d_in[8];
    const float* fc2w  = (const float*)d_in[9];
    const float* fc2b  = (const float*)d_in[10];
    float* out = (float*)d_out;

    build_k1_dense<<<4, 256>>>(w1, p1);
    build_k2_frag<<<200, 256>>>(w2, p2);
    build_w1_frag<<<1600, 256>>>(fc1w);
    build_tab<<<4, 256>>>();
    conv1_kernel<<<4096, 448>>>(x, b1);

    cudaFuncSetAttribute(conv2_kernel, cudaFuncAttributeMaxDynamicSharedMemorySize, C2_SMEM_BYTES);
    conv2_kernel<<<4096, 416, C2_SMEM_BYTES>>>(b2);

    cudaFuncSetAttribute(fc1_kernel, cudaFuncAttributeMaxDynamicSharedMemorySize, FC1_SMEM_BYTES);
    fc1_kernel<<<128, 256, FC1_SMEM_BYTES>>>(fc1b);

    fc2_kernel<<<160, 256>>>(fc2w, fc2b, out);
}

// round 10
// speedup vs baseline: 3.1012x; 1.0365x over previous
#include <cuda_runtime.h>
#include <cuda_bf16.h>
#include <math.h>
#include <stdint.h>

// ================= scratch (device globals: allocation-free) =================
__device__ __nv_bfloat16 g_K1fh[1024];           // conv1 W hi, frag layout (2 ks x 4 n8 x 2 reg x 32 ln)
__device__ __nv_bfloat16 g_K1fl[1024];           // conv1 W lo
__device__ __nv_bfloat16 g_Bh[64000];            // conv2 W hi, frag layout, lane-stride 20 words
__device__ __nv_bfloat16 g_Bl[64000];            // conv2 W lo
__device__ __nv_bfloat16 g_W1h[409600];          // fc1 W hi, frag layout
__device__ __nv_bfloat16 g_W1l[409600];          // fc1 W lo
__device__ float g_h1[4096 * 196 * 32];          // conv1 out pos-major [b][pos][ic]
__device__ __nv_bfloat16 g_Ah[4096 * 3200];      // conv2 out hi (fc1 A), K padded to 3200 (pad=0)
__device__ __nv_bfloat16 g_Al[4096 * 3200];      // conv2 out lo
__device__ float g_f1[4096 * 128];               // fc1 output

// ================= helpers =================
__device__ __forceinline__ uint32_t smem_u32(const void* p) {
    return (uint32_t)__cvta_generic_to_shared(p);
}
#define CP_ASYNC16(dst_u32, src_ptr) \
    asm volatile("cp.async.cg.shared.global [%0], [%1], 16;" :: "r"(dst_u32), "l"(src_ptr))
#define CP_COMMIT() asm volatile("cp.async.commit_group;")
#define CP_WAIT0() asm volatile("cp.async.wait_group 0;" ::: "memory")

__device__ __forceinline__ void mma_bf16(float* c, uint32_t a0, uint32_t a1,
                                         uint32_t a2, uint32_t a3,
                                         uint32_t b0, uint32_t b1) {
    asm volatile(
        "mma.sync.aligned.m16n8k16.row.col.f32.bf16.bf16.f32 "
        "{%0,%1,%2,%3}, {%4,%5,%6,%7}, {%8,%9}, {%0,%1,%2,%3};"
        : "+f"(c[0]), "+f"(c[1]), "+f"(c[2]), "+f"(c[3])
        : "r"(a0), "r"(a1), "r"(a2), "r"(a3), "r"(b0), "r"(b1));
}

__device__ __forceinline__ void pack_pair(float a, float b, uint32_t& h, uint32_t& l) {
    __nv_bfloat162 hp = __floats2bfloat162_rn(a, b);
    uint32_t hu = *(uint32_t*)&hp;
    float ra = a - __uint_as_float(hu << 16);
    float rb = b - __uint_as_float(hu & 0xFFFF0000u);
    __nv_bfloat162 lp = __floats2bfloat162_rn(ra, rb);
    h = hu;
    l = *(uint32_t*)&lp;
}

// ================= DCLS dense-kernel builders =================
// conv1: dense DCLS -> bf16 hi/lo in HMMA B-frag layout. k 0..31 (>=25 zero), oc 0..31.
__global__ void build_k1_frag(const float* __restrict__ w1, const float* __restrict__ p1) {
    int t = blockIdx.x * 256 + threadIdx.x;
    if (t >= 1024) return;
    int k  = t >> 5;        // 0..31
    int oc = t & 31;
    float s = 0.f;
    if (k < 25) {
        int ii = k / 5, jj = k - ii * 5;
        #pragma unroll 4
        for (int kc = 0; kc < 16; kc++) {
            int e = oc * 16 + kc;
            float w  = w1[e];
            float pa = fminf(fmaxf(p1[e],       -2.f), 2.f) + 2.f;
            float pb = fminf(fmaxf(p1[512 + e], -2.f), 2.f) + 2.f;
            int i1 = (int)floorf(pa), i2 = (int)floorf(pb);
            float r1 = pa - (float)i1, r2 = pb - (float)i2;
            if (i1     == ii && i2     == jj) s += w * (1.f - r1) * (1.f - r2);
            if (i1 + 1 == ii && i2     == jj) s += w * r1 * (1.f - r2);
            if (i1     == ii && i2 + 1 == jj) s += w * (1.f - r1) * r2;
            if (i1 + 1 == ii && i2 + 1 == jj) s += w * r1 * r2;
        }
    }
    __nv_bfloat16 hi = __float2bfloat16(s);
    __nv_bfloat16 lo = __float2bfloat16(s - __bfloat162float(hi));
    int ts = k >> 4, kk = k & 15;
    int reg = kk >> 3, half = kk & 1;
    int ln  = ((kk >> 1) & 3) + (oc & 7) * 4;
    int n8  = oc >> 3;
    int word = ((ts * 4 + n8) * 2 + reg) * 32 + ln;
    g_K1fh[2 * word + half] = hi;
    g_K1fl[2 * word + half] = lo;
}

// conv2 W -> bf16 hi/lo, frag layout: chunk c(5 ksteps): word = c*3200 + (tp*32+ln)*20 + n8*2 + reg
__global__ void build_k2_frag(const float* __restrict__ w2, const float* __restrict__ p2) {
    int t = blockIdx.x * 256 + threadIdx.x;
    if (t >= 800 * 64) return;
    int k  = t >> 6;        // 0..799
    int oc = t & 63;
    int ci = k / 25; int cell = k - ci * 25;
    int ii = cell / 5, jj = cell - ii * 5;
    float s = 0.f;
    #pragma unroll 4
    for (int kc = 0; kc < 32; kc++) {
        int e = oc * 1024 + ci * 32 + kc;
        float w  = w2[e];
        float pa = fminf(fmaxf(p2[e],         -2.f), 2.f) + 2.f;
        float pb = fminf(fmaxf(p2[65536 + e], -2.f), 2.f) + 2.f;
        int i1 = (int)floorf(pa), i2 = (int)floorf(pb);
        float r1 = pa - (float)i1, r2 = pb - (float)i2;
        if (i1     == ii && i2     == jj) s += w * (1.f - r1) * (1.f - r2);
        if (i1 + 1 == ii && i2     == jj) s += w * r1 * (1.f - r2);
        if (i1     == ii && i2 + 1 == jj) s += w * (1.f - r1) * r2;
        if (i1 + 1 == ii && i2 + 1 == jj) s += w * r1 * r2;
    }
    __nv_bfloat16 hi = __float2bfloat16(s);
    __nv_bfloat16 lo = __float2bfloat16(s - __bfloat162float(hi));
    int ts = k >> 4, kk = k & 15;
    int reg = kk >> 3, half = kk & 1;
    int ln  = ((kk >> 1) & 3) + (oc & 7) * 4;
    int n8  = oc >> 3;
    int c   = ts / 5, tp = ts - c * 5;
    int w = c * 3200 + (tp * 32 + ln) * 20 + n8 * 2 + reg;
    g_Bh[2 * w + half] = hi;
    g_Bl[2 * w + half] = lo;
}

// fc1 W -> bf16 hi/lo, frag layout: word = ((ts*4+nq)*32+ln)*8 + n8l*2 + reg
__global__ void build_w1_frag(const float* __restrict__ w) {
    int t = blockIdx.x * 256 + threadIdx.x;
    if (t >= 128 * 3200) return;
    int n = t / 3200; int k = t - n * 3200;
    float v = 0.f;
    if (k < 3136) {
        int p = k >> 6, oc = k & 63;
        v = w[n * 3136 + oc * 49 + p];
    }
    __nv_bfloat16 hi = __float2bfloat16(v);
    __nv_bfloat16 lo = __float2bfloat16(v - __bfloat162float(hi));
    int ts = k >> 4, kk = k & 15;
    int reg = kk >> 3, half = kk & 1;
    int ln  = ((kk >> 1) & 3) + (n & 7) * 4;
    int n8  = n >> 3;
    int nq = n8 >> 2, n8l = n8 & 3;
    int word = ((ts * 4 + nq) * 32 + ln) * 8 + n8l * 2 + reg;
    g_W1h[2 * word + half] = hi;
    g_W1l[2 * word + half] = lo;
}

// ================= conv1: bf16-split HMMA, register pooling =================
// CTA = image, 416 threads = 13 warps. M = 4 quadrants x 208 pooled slots (196 valid).
// Pool = elementwise max over the 4 quadrant accumulators in registers.
__global__ __launch_bounds__(416, 1) void conv1_kernel(const float* __restrict__ x,
                                                       const float* __restrict__ b1) {
    __shared__ float sImg[1024];       // 32x32 haloed image
    __shared__ uint32_t sBh[512];      // conv1 W hi frags
    __shared__ uint32_t sBl[512];
    int b = blockIdx.x;
    int tid = threadIdx.x;
    int lane = tid & 31;
    int warp = tid >> 5;   // 0..12

    for (int i = tid; i < 1024; i += 416) sImg[i] = 0.f;
    for (int i = tid; i < 512; i += 416) {          // FIX: strided (416 < 512)
        sBh[i] = ((const uint32_t*)g_K1fh)[i];
        sBl[i] = ((const uint32_t*)g_K1fl)[i];
    }
    __syncthreads();
    const float* xb = x + (long)b * 784;
    for (int i = tid; i < 784; i += 416) {
        int r = i / 28, c = i - r * 28;
        sImg[(r + 2) * 32 + c + 2] = xb[i];
    }
    __syncthreads();

    int pp0 = warp * 16 + (lane >> 2);
    int pp1 = pp0 + 8;
    bool v0 = pp0 < 196, v1 = pp1 < 196;
    int pr0 = pp0 / 14, pc0 = pp0 - pr0 * 14;
    int pr1 = pp1 / 14, pc1 = pp1 - pr1 * 14;
    int b0q[4], b1q[4];
    #pragma unroll
    for (int q = 0; q < 4; q++) {
        int qr = q >> 1, qc = q & 1;
        b0q[q] = v0 ? (2 * pr0 + qr) * 32 + (2 * pc0 + qc) : 0;
        b1q[q] = v1 ? (2 * pr1 + qr) * 32 + (2 * pc1 + qc) : 0;
    }
    int kq = 2 * (lane & 3);
    int off[8]; bool kv[8];
    #pragma unroll
    for (int i = 0; i < 8; i++) {
        int k = kq + (i & 1) + ((i >> 1) & 1) * 8 + (i >> 2) * 16;
        kv[i] = k < 25;
        int ky = k / 5, kx = k - ky * 5;
        off[i] = kv[i] ? ky * 32 + kx : 0;
    }

    float acc[4][4][4];
    #pragma unroll
    for (int q = 0; q < 4; q++)
        #pragma unroll
        for (int n8 = 0; n8 < 4; n8++)
            #pragma unroll
            for (int j = 0; j < 4; j++) acc[q][n8][j] = 0.f;

    #pragma unroll
    for (int ts = 0; ts < 2; ts++) {
        uint32_t bh[4][2], bl[4][2];
        #pragma unroll
        for (int n8 = 0; n8 < 4; n8++) {
            bh[n8][0] = sBh[((ts * 4 + n8) * 2 + 0) * 32 + lane];
            bh[n8][1] = sBh[((ts * 4 + n8) * 2 + 1) * 32 + lane];
            bl[n8][0] = sBl[((ts * 4 + n8) * 2 + 0) * 32 + lane];
            bl[n8][1] = sBl[((ts * 4 + n8) * 2 + 1) * 32 + lane];
        }
        int i0 = ts * 4;
        #pragma unroll
        for (int q = 0; q < 4; q++) {
            float a00 = (v0 && kv[i0])     ? sImg[b0q[q] + off[i0]]     : 0.f;
            float a01 = (v0 && kv[i0 + 1]) ? sImg[b0q[q] + off[i0 + 1]] : 0.f;
            float a08 = (v0 && kv[i0 + 2]) ? sImg[b0q[q] + off[i0 + 2]] : 0.f;
            float a09 = (v0 && kv[i0 + 3]) ? sImg[b0q[q] + off[i0 + 3]] : 0.f;
            float a10 = (v1 && kv[i0])     ? sImg[b1q[q] + off[i0]]     : 0.f;
            float a11 = (v1 && kv[i0 + 1]) ? sImg[b1q[q] + off[i0 + 1]] : 0.f;
            float a18 = (v1 && kv[i0 + 2]) ? sImg[b1q[q] + off[i0 + 2]] : 0.f;
            float a19 = (v1 && kv[i0 + 3]) ? sImg[b1q[q] + off[i0 + 3]] : 0.f;
            uint32_t ah0, ah1, ah2, ah3, al0, al1, al2, al3;
            pack_pair(a00, a01, ah0, al0);
            pack_pair(a10, a11, ah1, al1);
            pack_pair(a08, a09, ah2, al2);
            pack_pair(a18, a19, ah3, al3);
            #pragma unroll
            for (int n8 = 0; n8 < 4; n8++) {
                mma_bf16(acc[q][n8], ah0, ah1, ah2, ah3, bh[n8][0], bh[n8][1]);
                mma_bf16(acc[q][n8], ah0, ah1, ah2, ah3, bl[n8][0], bl[n8][1]);
                mma_bf16(acc[q][n8], al0, al1, al2, al3, bh[n8][0], bh[n8][1]);
            }
        }
    }

    // register pooling epilogue
    float* o = g_h1 + (long)b * 6272;
    #pragma unroll
    for (int n8 = 0; n8 < 4; n8++) {
        int oc = n8 * 8 + kq;
        float bb0 = b1[oc], bb1 = b1[oc + 1];
        if (v0) {
            float2 w;
            w.x = fmaxf(fmaxf(fmaxf(acc[0][n8][0], acc[1][n8][0]),
                              fmaxf(acc[2][n8][0], acc[3][n8][0])) + bb0, 0.f);
            w.y = fmaxf(fmaxf(fmaxf(acc[0][n8][1], acc[1][n8][1]),
                              fmaxf(acc[2][n8][1], acc[3][n8][1])) + bb1, 0.f);
            *(float2*)&o[pp0 * 32 + oc] = w;
        }
        if (v1) {
            float2 w;
            w.x = fmaxf(fmaxf(fmaxf(acc[0][n8][2], acc[1][n8][2]),
                              fmaxf(acc[2][n8][2], acc[3][n8][2])) + bb0, 0.f);
            w.y = fmaxf(fmaxf(fmaxf(acc[0][n8][3], acc[1][n8][3]),
                              fmaxf(acc[2][n8][3], acc[3][n8][3])) + bb1, 0.f);
            *(float2*)&o[pp1 * 32 + oc] = w;
        }
    }
}

// ================= conv2: bf16-split HMMA implicit GEMM =================
// CTA = image; 416 threads = 13 warps; warp = 16-row M tile (196 valid of 208).
#define C2_SMEM_BYTES (23908 * 4)

__global__ __launch_bounds__(416, 2) void conv2_kernel(const float* __restrict__ b2) {
    extern __shared__ float sm[];
    float* sImg = sm;                               // 10692
    uint32_t* sTab32 = (uint32_t*)(sm + 10692);     // 416
    uint32_t* Bbuf = (uint32_t*)(sm + 11108);       // 12800 words

    int b = blockIdx.x;
    int tid = threadIdx.x;
    int lane = tid & 31;
    int warp = tid >> 5;    // 0..12

    uint32_t BbufA = smem_u32(Bbuf);
    for (int i = tid; i < 800; i += 416) {
        CP_ASYNC16(BbufA + i * 16, (const char*)g_Bh + i * 16);
        CP_ASYNC16(BbufA + 12800 + i * 16, (const char*)g_Bl + i * 16);
    }
    CP_COMMIT();

    for (int i = tid; i < 10692; i += 416) sImg[i] = 0.f;
    if (tid < 416) {   // inline offset table: k -> (ky*18+kx)*33 + ic, packed 2 shorts/word
        uint32_t w = 0;
        #pragma unroll
        for (int h = 0; h < 2; h++) {
            int k = 2 * tid + h;
            int v = 0;
            if (k < 800) {
                int ic = k / 25; int tap = k - ic * 25;
                int ky = tap / 5, kx = tap - ky * 5;
                v = (ky * 18 + kx) * 33 + ic;
            }
            w |= ((uint32_t)(v & 0xFFFF)) << (16 * h);
        }
        sTab32[tid] = w;
    }
    __syncthreads();
    {
        const float* hb = g_h1 + (long)b * 6272;
        for (int i = tid; i < 6272; i += 416) {
            int ic = i & 31; int p = i >> 5;
            int rr = p / 14, cc = p - rr * 14;
            sImg[((rr + 2) * 18 + (cc + 2)) * 33 + ic] = hb[i];
        }
    }
    __syncthreads();

    int m0 = warp * 16 + (lane >> 2);
    int m1 = m0 + 8;
    bool vr0 = m0 < 196, vr1 = m1 < 196;
    int pr0 = m0 / 14, pc0 = m0 - pr0 * 14;
    int pr1 = m1 / 14, pc1 = m1 - pr1 * 14;
    int base0 = (pr0 * 18 + pc0) * 33;
    int base1 = (pr1 * 18 + pc1) * 33;
    int kq = 2 * (lane & 3);

    float acc[8][4];
    #pragma unroll
    for (int i = 0; i < 8; i++)
        #pragma unroll
        for (int j = 0; j < 4; j++) acc[i][j] = 0.f;

    for (int c = 0; c < 10; c++) {
        CP_WAIT0();
        __syncthreads();
        if (c < 9) {
            uint32_t dst = BbufA + ((c + 1) & 1) * 25600;
            const char* sh = (const char*)g_Bh + (c + 1) * 12800;
            const char* sl = (const char*)g_Bl + (c + 1) * 12800;
            for (int i = tid; i < 800; i += 416) {
                CP_ASYNC16(dst + i * 16, sh + i * 16);
                CP_ASYNC16(dst + 12800 + i * 16, sl + i * 16);
            }
            CP_COMMIT();
        }
        const uint32_t* Bc = Bbuf + (c & 1) * 6400;

        #pragma unroll
        for (int tp = 0; tp < 5; tp++) {
            int k0 = (c * 5 + tp) * 16 + kq;
            uint32_t t01 = sTab32[k0 >> 1];
            uint32_t t89 = sTab32[(k0 >> 1) + 4];
            int o0 = (int)(short)(t01 & 0xFFFF), o1 = (int)(short)(t01 >> 16);
            int o8 = (int)(short)(t89 & 0xFFFF), o9 = (int)(short)(t89 >> 16);
            float v00 = vr0 ? sImg[base0 + o0] : 0.f;
            float v01 = vr0 ? sImg[base0 + o1] : 0.f;
            float v08 = vr0 ? sImg[base0 + o8] : 0.f;
            float v09 = vr0 ? sImg[base0 + o9] : 0.f;
            float v10 = vr1 ? sImg[base1 + o0] : 0.f;
            float v11 = vr1 ? sImg[base1 + o1] : 0.f;
            float v18 = vr1 ? sImg[base1 + o8] : 0.f;
            float v19 = vr1 ? sImg[base1 + o9] : 0.f;

            uint32_t ah0, ah1, ah2, ah3, al0, al1, al2, al3;
            pack_pair(v00, v01, ah0, al0);
            pack_pair(v10, v11, ah1, al1);
            pack_pair(v08, v09, ah2, al2);
            pack_pair(v18, v19, ah3, al3);

            const uint32_t* bpH = Bc + (tp * 32 + lane) * 20;
            const uint32_t* bpL = bpH + 3200;
            #pragma unroll
            for (int q = 0; q < 4; q++) {
                uint4 h4 = *(const uint4*)&bpH[q * 4];
                uint4 l4 = *(const uint4*)&bpL[q * 4];
                mma_bf16(acc[2 * q],     ah0, ah1, ah2, ah3, h4.x, h4.y);
                mma_bf16(acc[2 * q],     ah0, ah1, ah2, ah3, l4.x, l4.y);
                mma_bf16(acc[2 * q],     al0, al1, al2, al3, h4.x, h4.y);
                mma_bf16(acc[2 * q + 1], ah0, ah1, ah2, ah3, h4.z, h4.w);
                mma_bf16(acc[2 * q + 1], ah0, ah1, ah2, ah3, l4.z, l4.w);
                mma_bf16(acc[2 * q + 1], al0, al1, al2, al3, h4.z, h4.w);
            }
        }
    }

    // epilogue: acc -> smem, 2x2 pool + bias + relu, split to bf16 hi/lo [b][p*64+oc]
    __syncthreads();
    float* pool = sm;     // 196 x 66
    #pragma unroll
    for (int n8 = 0; n8 < 8; n8++) {
        int col = n8 * 8 + kq;
        if (vr0) { pool[m0 * 66 + col] = acc[n8][0]; pool[m0 * 66 + col + 1] = acc[n8][1]; }
        if (vr1) { pool[m1 * 66 + col] = acc[n8][2]; pool[m1 * 66 + col + 1] = acc[n8][3]; }
    }
    __syncthreads();
    __nv_bfloat16* outH = g_Ah + (long)b * 3200;
    __nv_bfloat16* outL = g_Al + (long)b * 3200;
    for (int i = tid; i < 3136; i += 416) {
        int oc = i & 63; int pp = i >> 6;
        int pr = pp / 7, pc = pp - pr * 7;
        int ma = (2 * pr) * 14 + 2 * pc;
        float v = fmaxf(fmaxf(pool[ma * 66 + oc],        pool[(ma + 1) * 66 + oc]),
                        fmaxf(pool[(ma + 14) * 66 + oc], pool[(ma + 15) * 66 + oc]));
        v = fmaxf(v + b2[oc], 0.f);
        __nv_bfloat16 hi = __float2bfloat16(v);
        __nv_bfloat16 lo = __float2bfloat16(v - __bfloat162float(hi));
        outH[i] = hi;
        outL[i] = lo;
    }
}

// ================= FC1: bf16-split HMMA GEMM (4096x128x3200) =================
#define FC1_SMEM_BYTES ((5632 + 20480) * 4)

__global__ __launch_bounds__(256, 1) void fc1_kernel(const float* __restrict__ bias) {
    extern __shared__ uint32_t smw[];
    uint32_t* sA = smw;            // 2 x 2816
    uint32_t* sB = smw + 5632;     // 2 x 10240
    int tid = threadIdx.x;
    int lane = tid & 31;
    int warp = tid >> 5;
    int wm = warp & 1, wn = warp >> 1;
    int mBase = blockIdx.x * 32;

    uint32_t sAaddr = smem_u32(sA);
    uint32_t sBaddr = smem_u32(sB);

    {
        for (int i = tid; i < 320; i += 256) {
            int row = i / 10, g = i - row * 10;
            long so = ((long)(mBase + row) * 3200) * 2 + g * 16;
            CP_ASYNC16(sAaddr + row * 176 + g * 16, (const char*)g_Ah + so);
            CP_ASYNC16(sAaddr + 5632 + row * 176 + g * 16, (const char*)g_Al + so);
        }
        for (int i = tid; i < 1280; i += 256) {
            CP_ASYNC16(sBaddr + i * 16, (const char*)g_W1h + i * 16);
            CP_ASYNC16(sBaddr + 20480 + i * 16, (const char*)g_W1l + i * 16);
        }
        CP_COMMIT();
    }

    float acc[4][4];
    #pragma unroll
    for (int i = 0; i < 4; i++)
        #pragma unroll
        for (int j = 0; j < 4; j++) acc[i][j] = 0.f;

    int r0w = (wm * 16 + (lane >> 2)) * 44;
    int r1w = r0w + 8 * 44;

    for (int c = 0; c < 40; c++) {
        CP_WAIT0();
        __syncthreads();
        if (c < 39) {
            int p = (c + 1) & 1;
            uint32_t dA = sAaddr + p * 11264;
            for (int i = tid; i < 320; i += 256) {
                int row = i / 10, g = i - row * 10;
                long so = ((long)(mBase + row) * 3200 + (c + 1) * 80) * 2 + g * 16;
                CP_ASYNC16(dA + row * 176 + g * 16, (const char*)g_Ah + so);
                CP_ASYNC16(dA + 5632 + row * 176 + g * 16, (const char*)g_Al + so);
            }
            uint32_t dB = sBaddr + p * 40960;
            for (int i = tid; i < 1280; i += 256) {
                CP_ASYNC16(dB + i * 16, (const char*)g_W1h + (c + 1) * 20480 + i * 16);
                CP_ASYNC16(dB + 20480 + i * 16, (const char*)g_W1l + (c + 1) * 20480 + i * 16);
            }
            CP_COMMIT();
        }
        const uint32_t* Ab = sA + (c & 1) * 2816;
        const uint32_t* Bb = sB + (c & 1) * 10240;

        #pragma unroll
        for (int tp = 0; tp < 5; tp++) {
            int aw = tp * 8 + (lane & 3);
            uint32_t ah0 = Ab[r0w + aw],        ah1 = Ab[r1w + aw];
            uint32_t ah2 = Ab[r0w + aw + 4],    ah3 = Ab[r1w + aw + 4];
            uint32_t al0 = Ab[1408 + r0w + aw],     al1 = Ab[1408 + r1w + aw];
            uint32_t al2 = Ab[1408 + r0w + aw + 4], al3 = Ab[1408 + r1w + aw + 4];
            const uint32_t* bpH = Bb + ((tp * 4 + wn) * 32 + lane) * 8;
            const uint32_t* bpL = bpH + 5120;
            uint4 h0 = *(const uint4*)&bpH[0];
            uint4 h1 = *(const uint4*)&bpH[4];
            uint4 l0 = *(const uint4*)&bpL[0];
            uint4 l1 = *(const uint4*)&bpL[4];
            mma_bf16(acc[0], ah0, ah1, ah2, ah3, h0.x, h0.y);
            mma_bf16(acc[0], ah0, ah1, ah2, ah3, l0.x, l0.y);
            mma_bf16(acc[0], al0, al1, al2, al3, h0.x, h0.y);
            mma_bf16(acc[1], ah0, ah1, ah2, ah3, h0.z, h0.w);
            mma_bf16(acc[1], ah0, ah1, ah2, ah3, l0.z, l0.w);
            mma_bf16(acc[1], al0, al1, al2, al3, h0.z, h0.w);
            mma_bf16(acc[2], ah0, ah1, ah2, ah3, h1.x, h1.y);
            mma_bf16(acc[2], ah0, ah1, ah2, ah3, l1.x, l1.y);
            mma_bf16(acc[2], al0, al1, al2, al3, h1.x, h1.y);
            mma_bf16(acc[3], ah0, ah1, ah2, ah3, h1.z, h1.w);
            mma_bf16(acc[3], ah0, ah1, ah2, ah3, l1.z, l1.w);
            mma_bf16(acc[3], al0, al1, al2, al3, h1.z, h1.w);
        }
    }

    int row = wm * 16 + (lane >> 2);
    int m = mBase + row;
    int colb = wn * 32 + 2 * (lane & 3);
    #pragma unroll
    for (int q = 0; q < 4; q++) {
        int n0 = colb + q * 8;
        g_f1[m * 128 + n0]           = fmaxf(acc[q][0] + bias[n0], 0.f);
        g_f1[m * 128 + n0 + 1]       = fmaxf(acc[q][1] + bias[n0 + 1], 0.f);
        g_f1[(m + 8) * 128 + n0]     = fmaxf(acc[q][2] + bias[n0], 0.f);
        g_f1[(m + 8) * 128 + n0 + 1] = fmaxf(acc[q][3] + bias[n0 + 1], 0.f);
    }
}

// ================= FC2 =================
__global__ __launch_bounds__(256) void fc2_kernel(const float* __restrict__ w,
                                                  const float* __restrict__ bias,
                                                  float* __restrict__ out) {
    int idx = blockIdx.x * 256 + threadIdx.x;
    if (idx >= 4096 * 10) return;
    int b = idx / 10, n = idx - b * 10;
    const float* h  = g_f1 + (long)b * 128;
    const float* wr = w + n * 128;
    float s = bias[n];
    #pragma unroll 8
    for (int k = 0; k < 128; k++) s += h[k] * wr[k];
    out[idx] = s;
}

// ================= launcher =================
extern "C" void kernel_launch(void* const* d_in, const int* in_sizes, int n_in,
                              void* d_out, int out_size) {
    const float* x     = (const float*)d_in[0];
    const float* w1    = (const float*)d_in[1];
    const float* p1    = (const float*)d_in[2];
    const float* b1    = (const float*)d_in[3];
    const float* w2    = (const float*)d_in[4];
    const float* p2    = (const float*)d_in[5];
    const float* b2    = (const float*)d_in[6];
    const float* fc1w  = (const float*)d_in[7];
    const float* fc1b  = (const float*)d_in[8];
    const float* fc2w  = (const float*)d_in[9];
    const float* fc2b  = (const float*)d_in[10];
    float* out = (float*)d_out;

    // launch index 3 (conv2) is the one ncu profiles
    build_k1_frag<<<4, 256>>>(w1, p1);
    build_k2_frag<<<200, 256>>>(w2, p2);
    conv1_kernel<<<4096, 416>>>(x, b1);

    cudaFuncSetAttribute(conv2_kernel, cudaFuncAttributeMaxDynamicSharedMemorySize, C2_SMEM_BYTES);
    conv2_kernel<<<4096, 416, C2_SMEM_BYTES>>>(b2);

    build_w1_frag<<<1600, 256>>>(fc1w);

    cudaFuncSetAttribute(fc1_kernel, cudaFuncAttributeMaxDynamicSharedMemorySize, FC1_SMEM_BYTES);
    fc1_kernel<<<128, 256, FC1_SMEM_BYTES>>>(fc1b);

    fc2_kernel<<<160, 256>>>(fc2w, fc2b, out);
}